// round 3
// baseline (speedup 1.0000x reference)
#include <cuda_runtime.h>
#include <math.h>

#define BB 16
#define NN 1026
#define NGT 1024
#define CC 768
#define HH 12
#define HD 64

// ---------------- scratch (device globals; no runtime allocation) ----------------
__device__ float g_xln[BB * NN * CC];          // layernormed tokens         (~50 MB)
__device__ float g_kv[BB * NN * 1536];         // K (cols 0..767) | V (768..1535) (~101 MB)
__device__ float g_att0[BB * HH * NGT];        // per-head cls->general probs
__device__ float g_att1[BB * HH * NGT];        // per-head box->general probs
__device__ float g_out_rows[BB * 18 * CC];     // attention outputs for the 18 needed rows
__device__ float g_base[BB * 18 * CC];         // residual base rows (cls/box/gathered general)
__device__ int   g_idx[BB * 16];               // routed token indices

// ---------------- kernel 1: layernorm over all 16416 tokens ----------------
__global__ void ln_kernel(const float* __restrict__ gen, const float* __restrict__ cls,
                          const float* __restrict__ box, const float* __restrict__ gamma,
                          const float* __restrict__ beta) {
    int tkn = blockIdx.x;
    int b = tkn / NN, n = tkn % NN;
    const float* src;
    if (n == 0)      src = cls + (size_t)b * CC;
    else if (n == 1) src = box + (size_t)b * CC;
    else             src = gen + ((size_t)b * NGT + (n - 2)) * CC;

    int t = threadIdx.x;
    float v[3];
    float s = 0.f, ss = 0.f;
#pragma unroll
    for (int i = 0; i < 3; i++) {
        v[i] = src[t + i * 256];
        s += v[i];
        ss += v[i] * v[i];
    }
    __shared__ float rs[8], rss[8], stat[2];
    for (int o = 16; o > 0; o >>= 1) {
        s  += __shfl_xor_sync(0xffffffffu, s, o);
        ss += __shfl_xor_sync(0xffffffffu, ss, o);
    }
    if ((t & 31) == 0) { rs[t >> 5] = s; rss[t >> 5] = ss; }
    __syncthreads();
    if (t == 0) {
        float S = 0.f, SS = 0.f;
        for (int i = 0; i < 8; i++) { S += rs[i]; SS += rss[i]; }
        float m = S / (float)CC;
        float var = SS / (float)CC - m * m;
        stat[0] = m;
        stat[1] = rsqrtf(var + 1e-5f);
    }
    __syncthreads();
    float m = stat[0], inv = stat[1];
    float* dst = g_xln + (size_t)tkn * CC;
#pragma unroll
    for (int i = 0; i < 3; i++) {
        int c = t + i * 256;
        dst[c] = (v[i] - m) * inv * gamma[c] + beta[c];
    }
}

// ---------------- generic fp32 tiled GEMM: C = A @ B^T ----------------
// EPI==0: A=g_xln, C=g_kv   (K,V projection)
// EPI==1: A=g_out_rows, epilogue = +bias +base, scatter into final output
template <int EPI>
__global__ void gemm_kernel(const float* __restrict__ Bm, int M, int N, int K,
                            const float* __restrict__ bias, float* __restrict__ outp) {
    __shared__ float As[16][64];
    __shared__ float Bs[16][64];
    int t = threadIdx.x;
    int mb = blockIdx.y * 64, nb = blockIdx.x * 64;
    int lr = t >> 2;            // 0..63
    int lc = (t & 3) << 2;      // 0,4,8,12
    int tx = t & 15, ty = t >> 4;
    float acc[4][4];
#pragma unroll
    for (int i = 0; i < 4; i++)
#pragma unroll
        for (int j = 0; j < 4; j++) acc[i][j] = 0.f;

    const float* A = EPI ? g_out_rows : g_xln;
    const float* Ap = A + (size_t)(mb + lr) * K + lc;
    const float* Bp = Bm + (size_t)(nb + lr) * K + lc;
    bool avalid = (mb + lr) < M;

    for (int kk = 0; kk < K; kk += 16) {
        float4 av = avalid ? *(const float4*)(Ap + kk) : make_float4(0.f, 0.f, 0.f, 0.f);
        float4 bv = *(const float4*)(Bp + kk);
        As[lc + 0][lr] = av.x; As[lc + 1][lr] = av.y; As[lc + 2][lr] = av.z; As[lc + 3][lr] = av.w;
        Bs[lc + 0][lr] = bv.x; Bs[lc + 1][lr] = bv.y; Bs[lc + 2][lr] = bv.z; Bs[lc + 3][lr] = bv.w;
        __syncthreads();
#pragma unroll
        for (int k = 0; k < 16; k++) {
            float4 a = *(const float4*)&As[k][ty << 2];
            float4 bq = *(const float4*)&Bs[k][tx << 2];
            float aa[4] = {a.x, a.y, a.z, a.w};
            float bb[4] = {bq.x, bq.y, bq.z, bq.w};
#pragma unroll
            for (int i = 0; i < 4; i++)
#pragma unroll
                for (int j = 0; j < 4; j++) acc[i][j] += aa[i] * bb[j];
        }
        __syncthreads();
    }

#pragma unroll
    for (int i = 0; i < 4; i++) {
        int row = mb + (ty << 2) + i;
        if (row < M) {
            if (EPI == 0) {
                float* cp = g_kv + (size_t)row * N + nb + (tx << 2);
#pragma unroll
                for (int j = 0; j < 4; j++) cp[j] = acc[i][j];
            } else {
                int b = row / 18, k = row % 18;
                size_t off;
                if (k == 0)      off = (size_t)(b * 9) * CC;                // cls_task slot 0
                else if (k == 1) off = (size_t)(144 + b * 9) * CC;          // box_task slot 0
                else if (k < 10) off = (size_t)(b * 9 + (k - 1)) * CC;      // cls_task slots 1..8
                else             off = (size_t)(144 + b * 9 + (k - 9)) * CC;// box_task slots 1..8
#pragma unroll
                for (int j = 0; j < 4; j++) {
                    int n = nb + (tx << 2) + j;
                    outp[off + n] = acc[i][j] + bias[n] + g_base[(size_t)row * CC + n];
                }
            }
        }
    }
}

// ---------------- kernel 3: attention rows 0 (cls) and 1 (box) ----------------
__global__ void attn01_kernel(const float* __restrict__ wqkv) {
    int bh = blockIdx.x;
    int b = bh / HH, h = bh % HH;
    __shared__ float sx[2][CC];
    __shared__ float sq[2][HD];
    __shared__ float sl[2][NN];
    __shared__ float wred[8];
    int t = threadIdx.x;

    for (int i = t; i < 2 * CC; i += 256)
        sx[i / CC][i % CC] = g_xln[(size_t)(b * NN + i / CC) * CC + (i % CC)];
    __syncthreads();

    if (t < 128) {  // q for rows 0,1: (r,d)
        int r = t >> 6, d = t & 63;
        const float4* w4 = (const float4*)(wqkv + (size_t)(h * HD + d) * CC);
        const float4* x4 = (const float4*)sx[r];
        float acc = 0.f;
#pragma unroll 4
        for (int c4 = 0; c4 < CC / 4; c4++) {
            float4 wv = w4[c4], xv = x4[c4];
            acc += wv.x * xv.x + wv.y * xv.y + wv.z * xv.z + wv.w * xv.w;
        }
        sq[r][d] = acc * 0.125f;  // hd^-0.5 folded into q
    }
    __syncthreads();

    for (int i = t; i < 2 * NN; i += 256) {  // logits
        int r = i / NN, j = i % NN;
        const float4* k4 = (const float4*)(g_kv + (size_t)(b * NN + j) * 1536 + h * HD);
        const float4* q4 = (const float4*)sq[r];
        float acc = 0.f;
#pragma unroll
        for (int d4 = 0; d4 < HD / 4; d4++) {
            float4 kv = k4[d4], qv = q4[d4];
            acc += kv.x * qv.x + kv.y * qv.y + kv.z * qv.z + kv.w * qv.w;
        }
        sl[r][j] = acc;
    }
    __syncthreads();
    if (t == 0) { sl[0][1] = 0.f; sl[1][0] = 0.f; }  // reference sets scaled logits to 0.0
    __syncthreads();

    // softmax: threads [0,128) -> row 0, [128,256) -> row 1
    int r = t >> 7, lt = t & 127, w = t >> 5;
    float mx = -1e30f;
    for (int j = lt; j < NN; j += 128) mx = fmaxf(mx, sl[r][j]);
    for (int o = 16; o > 0; o >>= 1) mx = fmaxf(mx, __shfl_xor_sync(0xffffffffu, mx, o));
    if ((t & 31) == 0) wred[w] = mx;
    __syncthreads();
    mx = fmaxf(fmaxf(wred[r * 4 + 0], wred[r * 4 + 1]), fmaxf(wred[r * 4 + 2], wred[r * 4 + 3]));
    float sm = 0.f;
    for (int j = lt; j < NN; j += 128) { float e = expf(sl[r][j] - mx); sl[r][j] = e; sm += e; }
    for (int o = 16; o > 0; o >>= 1) sm += __shfl_xor_sync(0xffffffffu, sm, o);
    __syncthreads();
    if ((t & 31) == 0) wred[w] = sm;
    __syncthreads();
    float inv = 1.f / (wred[r * 4 + 0] + wred[r * 4 + 1] + wred[r * 4 + 2] + wred[r * 4 + 3]);
    for (int j = lt; j < NN; j += 128) sl[r][j] *= inv;
    __syncthreads();

    // store per-head probs over general tokens (for routing)
    for (int i = t; i < 2 * NGT; i += 256) {
        int rr = i / NGT, j = i % NGT;
        float p = sl[rr][2 + j];
        (rr == 0 ? g_att0 : g_att1)[(size_t)(b * HH + h) * NGT + j] = p;
    }
    // out rows 0,1 = attn @ V
    if (t < 128) {
        int r2 = t >> 6, d = t & 63;
        float acc = 0.f;
        const float* vp = g_kv + (size_t)(b * NN) * 1536 + CC + h * HD + d;
        for (int j = 0; j < NN; j++) acc += sl[r2][j] * vp[(size_t)j * 1536];
        g_out_rows[(size_t)(b * 18 + r2) * CC + h * HD + d] = acc;
    }
}

// ---------------- kernel 4: routing (sort + slot fill) + base gather ----------------
__global__ void route_kernel(const float* __restrict__ gen, const float* __restrict__ cls,
                             const float* __restrict__ box) {
    int b = blockIdx.x;
    int t = threadIdx.x;  // 1024 threads
    __shared__ unsigned long long key[NGT];
    __shared__ unsigned char sbox[NGT];
    __shared__ int sidx[16];

    float c = 0.f, bx = 0.f;
#pragma unroll
    for (int h = 0; h < HH; h++) {
        c  += g_att0[(size_t)(b * HH + h) * NGT + t];
        bx += g_att1[(size_t)(b * HH + h) * NGT + t];
    }
    float sum = c + bx;                    // positive -> float bits order == value order
    sbox[t] = (bx > c) ? 1 : 0;
    key[t] = ((unsigned long long)__float_as_uint(sum) << 32) |
             (unsigned long long)(0xFFFFFFFFu - (unsigned)t);   // stable: ties -> lower index first
    __syncthreads();

    for (int k = 2; k <= NGT; k <<= 1)
        for (int j = k >> 1; j > 0; j >>= 1) {
            int ixj = t ^ j;
            if (ixj > t) {
                unsigned long long a = key[t], d2 = key[ixj];
                bool desc = ((t & k) == 0);
                if (desc ? (a < d2) : (a > d2)) { key[t] = d2; key[ixj] = a; }
            }
            __syncthreads();
        }

    if (t == 0) {  // serial slot fill, replicating the reference's overwrite semantics
        int bj[16], cj[16];
        for (int i = 0; i < 16; i++) { bj[i] = -1; cj[i] = -1; }
        int br = 0, cr = 0;
        for (int p = 0; p < NGT; p++) {
            int orig = (int)(0xFFFFFFFFu - (unsigned)key[p]);
            if (sbox[orig]) { if (br < 16) bj[br] = p; br++; }
            else            { if (cr < 16) cj[15 - cr] = p; cr++; }
        }
        for (int s = 0; s < 16; s++) {
            int win = bj[s] > cj[s] ? bj[s] : cj[s];
            int id = 0;
            if (win >= 0) id = (int)(0xFFFFFFFFu - (unsigned)key[win]);
            sidx[s] = id;
            g_idx[b * 16 + s] = id;
        }
    }
    __syncthreads();

    for (int i = t; i < 18 * CC; i += 1024) {  // residual base rows
        int k = i / CC, ccc = i % CC;
        float v;
        if (k == 0)      v = cls[(size_t)b * CC + ccc];
        else if (k == 1) v = box[(size_t)b * CC + ccc];
        else             v = gen[((size_t)b * NGT + sidx[k - 2]) * CC + ccc];
        g_base[(size_t)(b * 18 + k) * CC + ccc] = v;
    }
}

// ---------------- kernel 5: attention for the 16 routed rows per (b,h) ----------------
// dynamic smem layout: [0,65664) logits(16x1026) overlapped w/ xs(16x768);
//                      [65664,69824) q(16x65 padded); [69824,103104) Ktile(128x65)
#define SMEM_SEL 103104
__global__ void attn_sel_kernel(const float* __restrict__ wqkv) {
    extern __shared__ char smc[];
    float* sl = (float*)smc;
    float* xs = (float*)smc;
    float* sq = (float*)(smc + 65664);
    float* kt = (float*)(smc + 69824);
    __shared__ int srow[16];

    int bh = blockIdx.x;
    int b = bh / HH, h = bh % HH;
    int t = threadIdx.x;

    if (t < 16) srow[t] = b * NN + 2 + g_idx[b * 16 + t];
    __syncthreads();
    for (int i = t; i < 16 * CC; i += 256)
        xs[i] = g_xln[(size_t)srow[i / CC] * CC + (i % CC)];
    __syncthreads();

    {  // q for 16 rows
        int d = t & 63, s0 = t >> 6;
        const float4* w4 = (const float4*)(wqkv + (size_t)(h * HD + d) * CC);
        float acc[4] = {0.f, 0.f, 0.f, 0.f};
        for (int c4 = 0; c4 < CC / 4; c4++) {
            float4 wv = w4[c4];
#pragma unroll
            for (int i = 0; i < 4; i++) {
                float4 xv = *(const float4*)&xs[(size_t)(s0 + 4 * i) * CC + c4 * 4];
                acc[i] += wv.x * xv.x + wv.y * xv.y + wv.z * xv.z + wv.w * xv.w;
            }
        }
#pragma unroll
        for (int i = 0; i < 4; i++) sq[(s0 + 4 * i) * 65 + d] = acc[i] * 0.125f;
    }
    __syncthreads();  // xs dead; sl region now writable

    for (int ch = 0; ch < 9; ch++) {  // logits in 128-key chunks via smem K tile
        int jbase = ch * 128;
        for (int i = t; i < 128 * 64; i += 256) {
            int jj = i >> 6, k = i & 63, j = jbase + jj;
            kt[jj * 65 + k] = (j < NN) ? g_kv[(size_t)(b * NN + j) * 1536 + h * HD + k] : 0.f;
        }
        __syncthreads();
        int jl = t & 31, sp = t >> 5;
        float a0[4] = {0.f, 0.f, 0.f, 0.f}, a1[4] = {0.f, 0.f, 0.f, 0.f};
        for (int k = 0; k < 64; k++) {
            float qa = sq[(sp * 2) * 65 + k], qb = sq[(sp * 2 + 1) * 65 + k];
#pragma unroll
            for (int u = 0; u < 4; u++) {
                float kv = kt[(jl + 32 * u) * 65 + k];
                a0[u] += qa * kv;
                a1[u] += qb * kv;
            }
        }
#pragma unroll
        for (int u = 0; u < 4; u++) {
            int j = jbase + jl + 32 * u;
            if (j < NN) {
                sl[(size_t)(sp * 2) * NN + j] = a0[u];
                sl[(size_t)(sp * 2 + 1) * NN + j] = a1[u];
            }
        }
        __syncthreads();
    }

    {  // softmax: warp w owns rows 2w, 2w+1 (no masking on general-token query rows)
        int w = t >> 5, lane = t & 31;
        for (int rr = 0; rr < 2; rr++) {
            int row = w * 2 + rr;
            float mx = -1e30f;
            for (int j = lane; j < NN; j += 32) mx = fmaxf(mx, sl[(size_t)row * NN + j]);
            for (int o = 16; o > 0; o >>= 1) mx = fmaxf(mx, __shfl_xor_sync(0xffffffffu, mx, o));
            float sm = 0.f;
            for (int j = lane; j < NN; j += 32) {
                float e = expf(sl[(size_t)row * NN + j] - mx);
                sl[(size_t)row * NN + j] = e;
                sm += e;
            }
            for (int o = 16; o > 0; o >>= 1) sm += __shfl_xor_sync(0xffffffffu, sm, o);
            float inv = 1.f / sm;
            for (int j = lane; j < NN; j += 32) sl[(size_t)row * NN + j] *= inv;
        }
    }
    __syncthreads();

    {  // out = P @ V
        int d = t & 63, s0 = t >> 6;
        float acc[4] = {0.f, 0.f, 0.f, 0.f};
        const float* vp = g_kv + (size_t)(b * NN) * 1536 + CC + h * HD + d;
        for (int j = 0; j < NN; j++) {
            float v = vp[(size_t)j * 1536];
#pragma unroll
            for (int i = 0; i < 4; i++) acc[i] += sl[(size_t)(s0 + 4 * i) * NN + j] * v;
        }
#pragma unroll
        for (int i = 0; i < 4; i++)
            g_out_rows[(size_t)(b * 18 + 2 + s0 + 4 * i) * CC + h * HD + d] = acc[i];
    }
}

// ---------------- launch ----------------
extern "C" void kernel_launch(void* const* d_in, const int* in_sizes, int n_in,
                              void* d_out, int out_size) {
    const float* gen   = (const float*)d_in[0];
    const float* cls   = (const float*)d_in[1];
    const float* box   = (const float*)d_in[2];
    const float* wqkv  = (const float*)d_in[3];
    const float* wproj = (const float*)d_in[4];
    const float* bproj = (const float*)d_in[5];
    const float* gamma = (const float*)d_in[6];
    const float* beta  = (const float*)d_in[7];
    float* out = (float*)d_out;

    cudaFuncSetAttribute(attn_sel_kernel, cudaFuncAttributeMaxDynamicSharedMemorySize, SMEM_SEL);

    // 1. LayerNorm
    ln_kernel<<<BB * NN, 256>>>(gen, cls, box, gamma, beta);
    // 2. K,V projection: (16416 x 768) @ (1536 x 768)^T
    {
        dim3 grid(1536 / 64, (BB * NN + 63) / 64);
        gemm_kernel<0><<<grid, 256>>>(wqkv + 768 * 768, BB * NN, 1536, CC, nullptr, nullptr);
    }
    // 3. attention rows 0,1 + per-head routing probs
    attn01_kernel<<<BB * HH, 256>>>(wqkv);
    // 4. routing + base gather
    route_kernel<<<BB, 1024>>>(gen, cls, box);
    // 5. attention for routed rows
    attn_sel_kernel<<<BB * HH, 256, SMEM_SEL>>>(wqkv);
    // 6. proj GEMM + bias + residual, scatter to output
    {
        dim3 grid(CC / 64, (BB * 18 + 63) / 64);
        gemm_kernel<1><<<grid, 256>>>(wproj, BB * 18, CC, CC, bproj, out);
    }
}

// round 15
// speedup vs baseline: 2.0395x; 2.0395x over previous
#include <cuda_runtime.h>
#include <math.h>

#define BB 16
#define NN 1026
#define NGT 1024
#define CC 768
#define HH 12
#define XST 1040   // xln rows per batch (padded; pad rows stay zero)
#define LP 1040    // padded logit row length
// row-in-batch layout for qw/L/T:  m = r*12 + h   (r-major)

// ---- scratch (device globals; zero-init; NEVER passed as kernel args from host) ----
__device__ __align__(128) float g_xln[BB * XST * CC];
__device__ __align__(128) float g_x18[BB * 18 * CC];
__device__ __align__(128) float g_q18[BB * 18 * CC];
__device__ __align__(128) float g_qw[BB * 216 * CC];
__device__ __align__(128) float g_L[BB * 216 * LP];
__device__ __align__(128) float g_T[BB * 216 * CC];
__device__ __align__(128) float g_att[BB * 18 * CC];
__device__ __align__(128) float g_base[BB * 18 * CC];
__device__ __align__(128) int   g_idx[BB * 16];

// ---------------- kernel 1: layernorm over all 16416 tokens ----------------
__global__ void ln_kernel(const float* __restrict__ gen, const float* __restrict__ cls,
                          const float* __restrict__ box, const float* __restrict__ gamma,
                          const float* __restrict__ beta) {
    int tkn = blockIdx.x;
    int b = tkn / NN, n = tkn % NN;
    const float* src;
    if (n == 0)      src = cls + (size_t)b * CC;
    else if (n == 1) src = box + (size_t)b * CC;
    else             src = gen + ((size_t)b * NGT + (n - 2)) * CC;

    int t = threadIdx.x;
    float v[3];
    float s = 0.f, ss = 0.f;
#pragma unroll
    for (int i = 0; i < 3; i++) {
        v[i] = src[t + i * 256];
        s += v[i];
        ss += v[i] * v[i];
    }
    __shared__ float rs[8], rss[8], stat[2];
    for (int o = 16; o > 0; o >>= 1) {
        s  += __shfl_xor_sync(0xffffffffu, s, o);
        ss += __shfl_xor_sync(0xffffffffu, ss, o);
    }
    if ((t & 31) == 0) { rs[t >> 5] = s; rss[t >> 5] = ss; }
    __syncthreads();
    if (t == 0) {
        float S = 0.f, SS = 0.f;
        for (int i = 0; i < 8; i++) { S += rs[i]; SS += rss[i]; }
        float m = S / (float)CC;
        float var = SS / (float)CC - m * m;
        stat[0] = m;
        stat[1] = rsqrtf(var + 1e-5f);
    }
    __syncthreads();
    float m = stat[0], inv = stat[1];
    float* dst = g_xln + ((size_t)b * XST + n) * CC;
#pragma unroll
    for (int i = 0; i < 3; i++) {
        int c = t + i * 256;
        float y = (v[i] - m) * inv * gamma[c] + beta[c];
        dst[c] = y;
        if (n < 2) g_x18[((size_t)(b * 18 + n)) * CC + c] = y;
    }
}

// ---------------- softmax over NN keys of g_L rows (in place, pad-zeroed) -------------
// blockIdx.x = b*S + m ; L row = b*216 + m ; r = m/12 (r-major layout)
__global__ void softmax_kernel(int S) {
    int b = blockIdx.x / S, m = blockIdx.x % S;
    int r = m / 12;
    int t = threadIdx.x;
    float* L = g_L + (size_t)(b * 216 + m) * LP;
    float v[9];
    float mx = -1e30f;
#pragma unroll
    for (int i = 0; i < 9; i++) {
        int j = t + (i << 7);
        if (j < NN) {
            float x = L[j];
            if (r == 0 && j == 1) x = 0.f;
            if (r == 1 && j == 0) x = 0.f;
            v[i] = x;
            mx = fmaxf(mx, x);
        } else v[i] = -1e30f;
    }
    __shared__ float sm_[4], ss_[4];
    int w = t >> 5, lane = t & 31;
    for (int o = 16; o > 0; o >>= 1) mx = fmaxf(mx, __shfl_xor_sync(0xffffffffu, mx, o));
    if (lane == 0) sm_[w] = mx;
    __syncthreads();
    mx = fmaxf(fmaxf(sm_[0], sm_[1]), fmaxf(sm_[2], sm_[3]));
    float s = 0.f;
#pragma unroll
    for (int i = 0; i < 9; i++) {
        int j = t + (i << 7);
        if (j < NN) { v[i] = expf(v[i] - mx); s += v[i]; }
    }
    for (int o = 16; o > 0; o >>= 1) s += __shfl_xor_sync(0xffffffffu, s, o);
    if (lane == 0) ss_[w] = s;
    __syncthreads();
    float inv = 1.f / (ss_[0] + ss_[1] + ss_[2] + ss_[3]);
#pragma unroll
    for (int i = 0; i < 9; i++) {
        int j = t + (i << 7);
        if (j < NN) L[j] = v[i] * inv;
    }
    if (t < LP - NN) L[NN + t] = 0.f;
}

// ---------------- routing: bitonic sort + serial slot fill (Round-1 proven) ----------
// probs from g_L rows m=h (r=0, cls) and m=12+h (r=1, box).
__global__ void route_kernel(const float* __restrict__ gen, const float* __restrict__ cls,
                             const float* __restrict__ box) {
    int b = blockIdx.x;
    int t = threadIdx.x;  // 1024 threads
    __shared__ unsigned long long key[NGT];
    __shared__ unsigned char sbox[NGT];
    __shared__ int sidx[16];

    float c = 0.f, bx = 0.f;
#pragma unroll
    for (int h = 0; h < HH; h++) {
        c  += g_L[((size_t)(b * 216 + h)) * LP + 2 + t];
        bx += g_L[((size_t)(b * 216 + 12 + h)) * LP + 2 + t];
    }
    float sum = c + bx;                    // positive -> float bits order == value order
    sbox[t] = (bx > c) ? 1 : 0;
    key[t] = ((unsigned long long)__float_as_uint(sum) << 32) |
             (unsigned long long)(0xFFFFFFFFu - (unsigned)t);   // stable ties
    __syncthreads();

    for (int k = 2; k <= NGT; k <<= 1)
        for (int j = k >> 1; j > 0; j >>= 1) {
            int ixj = t ^ j;
            if (ixj > t) {
                unsigned long long a = key[t], d2 = key[ixj];
                bool desc = ((t & k) == 0);
                if (desc ? (a < d2) : (a > d2)) { key[t] = d2; key[ixj] = a; }
            }
            __syncthreads();
        }

    if (t == 0) {
        int bj[16], cj[16];
        for (int i = 0; i < 16; i++) { bj[i] = -1; cj[i] = -1; }
        int br = 0, cr = 0;
        for (int p = 0; p < NGT; p++) {
            int orig = (int)(0xFFFFFFFFu - (unsigned)key[p]);
            if (sbox[orig]) { if (br < 16) bj[br] = p; br++; }
            else            { if (cr < 16) cj[15 - cr] = p; cr++; }
        }
        for (int s = 0; s < 16; s++) {
            int win = bj[s] > cj[s] ? bj[s] : cj[s];
            int id = 0;
            if (win >= 0) id = (int)(0xFFFFFFFFu - (unsigned)key[win]);
            sidx[s] = id;
            g_idx[b * 16 + s] = id;
        }
    }
    __syncthreads();

    for (int i = t; i < 18 * CC; i += 1024) {     // residual base (original tokens)
        int k = i / CC, cc2 = i % CC;
        float v;
        if (k == 0)      v = cls[(size_t)b * CC + cc2];
        else if (k == 1) v = box[(size_t)b * CC + cc2];
        else             v = gen[((size_t)b * NGT + sidx[k - 2]) * CC + cc2];
        g_base[((size_t)(b * 18 + k)) * CC + cc2] = v;
    }
    for (int i = t; i < 16 * CC; i += 1024) {     // x18 rows 2..17 (layernormed)
        int s = i / CC, cc2 = i % CC;
        g_x18[((size_t)(b * 18 + 2 + s)) * CC + cc2] =
            g_xln[((size_t)b * XST + 2 + sidx[s]) * CC + cc2];
    }
}

// ---------------- small GEMM (64x64 tile): C = scale * A @ W^T (N=K=768) --------------
// EPI==0: A=g_x18 -> g_q18.  EPI==1: A=g_att -> epilogue +bias +base, scatter to out.
template <int EPI>
__global__ void gemm_flat(const float* __restrict__ Bm, int M, float scale,
                          const float* __restrict__ bias, float* __restrict__ outp) {
    __shared__ float As[16][64];
    __shared__ float Bs[16][64];
    int t = threadIdx.x;
    int mb = blockIdx.y * 64, nb = blockIdx.x * 64;
    int lr = t >> 2, lc = (t & 3) << 2;
    int tx = t & 15, ty = t >> 4;
    float acc[4][4];
#pragma unroll
    for (int i = 0; i < 4; i++)
#pragma unroll
        for (int j = 0; j < 4; j++) acc[i][j] = 0.f;

    const float* A = EPI ? g_att : g_x18;          // device-side binding
    const float* Ap = A + (size_t)(mb + lr) * CC + lc;
    const float* Bp = Bm + (size_t)(nb + lr) * CC + lc;
    bool avalid = (mb + lr) < M;

    for (int kk = 0; kk < CC; kk += 16) {
        float4 av = avalid ? *(const float4*)(Ap + kk) : make_float4(0.f, 0.f, 0.f, 0.f);
        float4 bv = *(const float4*)(Bp + kk);
        As[lc + 0][lr] = av.x; As[lc + 1][lr] = av.y; As[lc + 2][lr] = av.z; As[lc + 3][lr] = av.w;
        Bs[lc + 0][lr] = bv.x; Bs[lc + 1][lr] = bv.y; Bs[lc + 2][lr] = bv.z; Bs[lc + 3][lr] = bv.w;
        __syncthreads();
#pragma unroll
        for (int k = 0; k < 16; k++) {
            float4 a = *(const float4*)&As[k][ty << 2];
            float4 bq = *(const float4*)&Bs[k][tx << 2];
            float aa[4] = {a.x, a.y, a.z, a.w};
            float bb[4] = {bq.x, bq.y, bq.z, bq.w};
#pragma unroll
            for (int i = 0; i < 4; i++)
#pragma unroll
                for (int j = 0; j < 4; j++) acc[i][j] += aa[i] * bb[j];
        }
        __syncthreads();
    }

#pragma unroll
    for (int i = 0; i < 4; i++) {
        int row = mb + (ty << 2) + i;
        if (row < M) {
            if (EPI == 0) {
                float* cp = g_q18 + (size_t)row * CC + nb + (tx << 2);
#pragma unroll
                for (int j = 0; j < 4; j++) cp[j] = acc[i][j] * scale;
            } else {
                int b = row / 18, k = row % 18;
                size_t off;
                if (k == 0)      off = (size_t)(b * 9) * CC;
                else if (k == 1) off = (size_t)(144 + b * 9) * CC;
                else if (k < 10) off = (size_t)(b * 9 + (k - 1)) * CC;
                else             off = (size_t)(144 + b * 9 + (k - 9)) * CC;
#pragma unroll
                for (int j = 0; j < 4; j++) {
                    int n = nb + (tx << 2) + j;
                    outp[off + n] = acc[i][j] + bias[n] + g_base[(size_t)row * CC + n];
                }
            }
        }
    }
}

// ---------------- per-head: qw = q18_h (18x64) @ Wk_h (64x768), r-major store ----------
__global__ void qw_head(const float* __restrict__ wqkv) {
    __shared__ float Ast[64][19];
    __shared__ float Wt[64][64];
    int t = threadIdx.x;
    int z = blockIdx.y;
    int b = z / HH, h = z % HH;
    int nb = blockIdx.x * 64;
    for (int i = t; i < 18 * 64; i += 256) {
        int r = i >> 6, d = i & 63;
        Ast[d][r] = g_q18[((size_t)(b * 18 + r)) * CC + h * 64 + d];
    }
    {
        int d = t >> 2, c0 = (t & 3) << 4;
        const float* wp = wqkv + ((size_t)(CC + h * 64 + d)) * CC + nb + c0;
        *(float4*)&Wt[d][c0]      = *(const float4*)wp;
        *(float4*)&Wt[d][c0 + 4]  = *(const float4*)(wp + 4);
        *(float4*)&Wt[d][c0 + 8]  = *(const float4*)(wp + 8);
        *(float4*)&Wt[d][c0 + 12] = *(const float4*)(wp + 12);
    }
    __syncthreads();
    int tx = t & 63, ty = t >> 6;
    float acc[5] = {0.f, 0.f, 0.f, 0.f, 0.f};
    for (int d = 0; d < 64; d++) {
        float w = Wt[d][tx];
#pragma unroll
        for (int i = 0; i < 5; i++) {
            int r = ty + (i << 2);
            if (r < 18) acc[i] += Ast[d][r] * w;
        }
    }
#pragma unroll
    for (int i = 0; i < 5; i++) {
        int r = ty + (i << 2);
        if (r < 18) g_qw[((size_t)(b * 216 + r * HH + h)) * CC + nb + tx] = acc[i];  // r-major
    }
}

// ---------------- per-head: out = T_h (18x768) @ Wv_h^T (768x64), r-major read --------
__global__ void vout_head(const float* __restrict__ wqkv) {
    __shared__ float Tt[18][64];
    __shared__ float Wt[64][65];   // 65-pad; scalar stores only (stride not 16B-aligned)
    int t = threadIdx.x;
    int z = blockIdx.x;
    int b = z / HH, h = z % HH;
    int tx = t & 63, ty = t >> 6;
    float acc[5] = {0.f, 0.f, 0.f, 0.f, 0.f};
    for (int cp = 0; cp < CC; cp += 64) {
        __syncthreads();
        for (int i = t; i < 18 * 64; i += 256) {
            int r = i >> 6, cc = i & 63;
            Tt[r][cc] = g_T[((size_t)(b * 216 + r * HH + h)) * CC + cp + cc];  // r-major
        }
        {
            int n = t >> 2, c0 = (t & 3) << 4;
            const float* wp = wqkv + ((size_t)(2 * CC + h * 64 + n)) * CC + cp + c0;
            float4 w0 = *(const float4*)wp;
            float4 w1 = *(const float4*)(wp + 4);
            float4 w2 = *(const float4*)(wp + 8);
            float4 w3 = *(const float4*)(wp + 12);
            Wt[n][c0 + 0]  = w0.x; Wt[n][c0 + 1]  = w0.y; Wt[n][c0 + 2]  = w0.z; Wt[n][c0 + 3]  = w0.w;
            Wt[n][c0 + 4]  = w1.x; Wt[n][c0 + 5]  = w1.y; Wt[n][c0 + 6]  = w1.z; Wt[n][c0 + 7]  = w1.w;
            Wt[n][c0 + 8]  = w2.x; Wt[n][c0 + 9]  = w2.y; Wt[n][c0 + 10] = w2.z; Wt[n][c0 + 11] = w2.w;
            Wt[n][c0 + 12] = w3.x; Wt[n][c0 + 13] = w3.y; Wt[n][c0 + 14] = w3.z; Wt[n][c0 + 15] = w3.w;
        }
        __syncthreads();
        for (int cc = 0; cc < 64; cc++) {
            float w = Wt[tx][cc];
#pragma unroll
            for (int i = 0; i < 5; i++) {
                int r = ty + (i << 2);
                if (r < 18) acc[i] += Tt[r][cc] * w;
            }
        }
    }
#pragma unroll
    for (int i = 0; i < 5; i++) {
        int r = ty + (i << 2);
        if (r < 18) g_att[((size_t)(b * 18 + r)) * CC + h * 64 + tx] = acc[i];
    }
}

// ---------------- big batched GEMM: 64x128 tile, 128 thr, 8x8 accum, prefetch ----------
// MODE 0: L = qw @ Xln^T   (TB=1, N=LP guarded)
// MODE 1: T = P(L) @ Xln   (TB=0, N=CC)
template <int MODE>
__global__ void gemm_big() {
    constexpr int TB  = (MODE == 0) ? 1 : 0;
    constexpr int M   = 216;
    constexpr int N   = (MODE == 0) ? LP : CC;
    constexpr int K   = (MODE == 0) ? CC : LP;
    constexpr int lda = (MODE == 0) ? CC : LP;
    constexpr int ldb = CC;
    constexpr int ldc = (MODE == 0) ? LP : CC;
    constexpr int NG  = (MODE == 0) ? 1 : 0;

    __shared__ float As[16][68];
    __shared__ float Bs[16][132];
    int t = threadIdx.x;
    int z = blockIdx.z;
    const float* A  = ((MODE == 0) ? g_qw : g_L) + (size_t)z * 216 * lda;
    const float* Bm = g_xln + (size_t)z * XST * CC;
    float*       C  = ((MODE == 0) ? g_L : g_T) + (size_t)z * 216 * ldc;
    int mb = blockIdx.y * 64, nb = blockIdx.x * 128;

    int ar = t >> 1, ak = (t & 1) << 3;
    bool aval = (mb + ar) < M;
    const float* Ap = A + (size_t)(mb + ar) * lda + ak;

    const float* Bp;
    bool bval = true;
    int bk = 0, bn8 = 0;
    if (TB) {
        if (NG) bval = (nb + t) < N;
        Bp = Bm + (size_t)(nb + t) * ldb;
    } else {
        bk = t >> 3; bn8 = (t & 7) << 4;
        Bp = Bm + (size_t)bk * ldb + nb + bn8;
    }

    float4 z4 = make_float4(0.f, 0.f, 0.f, 0.f);
    float4 a0, a1, b0, b1, b2, b3;
    a0 = aval ? *(const float4*)(Ap)     : z4;
    a1 = aval ? *(const float4*)(Ap + 4) : z4;
    if (TB) {
        b0 = bval ? *(const float4*)(Bp)      : z4;
        b1 = bval ? *(const float4*)(Bp + 4)  : z4;
        b2 = bval ? *(const float4*)(Bp + 8)  : z4;
        b3 = bval ? *(const float4*)(Bp + 12) : z4;
    } else {
        b0 = *(const float4*)(Bp);
        b1 = *(const float4*)(Bp + 4);
        b2 = *(const float4*)(Bp + 8);
        b3 = *(const float4*)(Bp + 12);
    }

    int tx = t & 15, ty = t >> 4;
    int m0 = ty << 3, n0 = tx << 3;
    float acc[8][8];
#pragma unroll
    for (int i = 0; i < 8; i++)
#pragma unroll
        for (int j = 0; j < 8; j++) acc[i][j] = 0.f;

    for (int kk = 0; kk < K; kk += 16) {
        As[ak + 0][ar] = a0.x; As[ak + 1][ar] = a0.y; As[ak + 2][ar] = a0.z; As[ak + 3][ar] = a0.w;
        As[ak + 4][ar] = a1.x; As[ak + 5][ar] = a1.y; As[ak + 6][ar] = a1.z; As[ak + 7][ar] = a1.w;
        if (TB) {
            Bs[0][t] = b0.x;  Bs[1][t] = b0.y;  Bs[2][t] = b0.z;  Bs[3][t] = b0.w;
            Bs[4][t] = b1.x;  Bs[5][t] = b1.y;  Bs[6][t] = b1.z;  Bs[7][t] = b1.w;
            Bs[8][t] = b2.x;  Bs[9][t] = b2.y;  Bs[10][t] = b2.z; Bs[11][t] = b2.w;
            Bs[12][t] = b3.x; Bs[13][t] = b3.y; Bs[14][t] = b3.z; Bs[15][t] = b3.w;
        } else {
            *(float4*)&Bs[bk][bn8]      = b0;
            *(float4*)&Bs[bk][bn8 + 4]  = b1;
            *(float4*)&Bs[bk][bn8 + 8]  = b2;
            *(float4*)&Bs[bk][bn8 + 12] = b3;
        }
        __syncthreads();
        int kn = kk + 16;
        if (kn < K) {
            a0 = aval ? *(const float4*)(Ap + kn)     : z4;
            a1 = aval ? *(const float4*)(Ap + kn + 4) : z4;
            if (TB) {
                b0 = bval ? *(const float4*)(Bp + kn)      : z4;
                b1 = bval ? *(const float4*)(Bp + kn + 4)  : z4;
                b2 = bval ? *(const float4*)(Bp + kn + 8)  : z4;
                b3 = bval ? *(const float4*)(Bp + kn + 12) : z4;
            } else {
                const float* bq = Bp + (size_t)kn * ldb;
                b0 = *(const float4*)(bq);
                b1 = *(const float4*)(bq + 4);
                b2 = *(const float4*)(bq + 8);
                b3 = *(const float4*)(bq + 12);
            }
        }
#pragma unroll
        for (int k = 0; k < 16; k++) {
            float am[8], bn_[8];
            *(float4*)&am[0]  = *(const float4*)&As[k][m0];
            *(float4*)&am[4]  = *(const float4*)&As[k][m0 + 4];
            *(float4*)&bn_[0] = *(const float4*)&Bs[k][n0];
            *(float4*)&bn_[4] = *(const float4*)&Bs[k][n0 + 4];
#pragma unroll
            for (int i = 0; i < 8; i++)
#pragma unroll
                for (int j = 0; j < 8; j++) acc[i][j] += am[i] * bn_[j];
        }
        __syncthreads();
    }

#pragma unroll
    for (int i = 0; i < 8; i++) {
        int row = mb + m0 + i;
        if (row < M) {
            float* cp = C + (size_t)row * ldc + nb + n0;
            if (!NG) {
                *(float4*)cp       = *(float4*)&acc[i][0];
                *(float4*)(cp + 4) = *(float4*)&acc[i][4];
            } else {
#pragma unroll
                for (int j = 0; j < 8; j++)
                    if (nb + n0 + j < N) cp[j] = acc[i][j];
            }
        }
    }
}

// ---------------- launch ----------------
extern "C" void kernel_launch(void* const* d_in, const int* in_sizes, int n_in,
                              void* d_out, int out_size) {
    const float* gen   = (const float*)d_in[0];
    const float* cls   = (const float*)d_in[1];
    const float* box   = (const float*)d_in[2];
    const float* wqkv  = (const float*)d_in[3];
    const float* wproj = (const float*)d_in[4];
    const float* bproj = (const float*)d_in[5];
    const float* gamma = (const float*)d_in[6];
    const float* beta  = (const float*)d_in[7];
    float* out = (float*)d_out;

    // 1. LayerNorm (stages x18 rows 0,1)
    ln_kernel<<<BB * NN, 256>>>(gen, cls, box, gamma, beta);

    // ---- PASS 1: compute L rows 0..23 per batch (depend only on x18 rows 0,1) ----
    gemm_flat<0><<<dim3(12, 5), 256>>>(wqkv, BB * 18, 0.125f, nullptr, nullptr);
    qw_head<<<dim3(12, BB * HH), 256>>>(wqkv);
    gemm_big<0><<<dim3(9, 1, BB), 128>>>();      // m-tile 0 only (rows 0..63)
    softmax_kernel<<<BB * 24, 128>>>(24);        // rows m=0..23 (r=0,1 all heads)

    // 2. Routing + gathers (g_base, x18 rows 2..17)
    route_kernel<<<BB, 1024>>>(gen, cls, box);

    // ---- PASS 2: full phase C on gathered x18 ----
    gemm_flat<0><<<dim3(12, 5), 256>>>(wqkv, BB * 18, 0.125f, nullptr, nullptr);
    qw_head<<<dim3(12, BB * HH), 256>>>(wqkv);
    gemm_big<0><<<dim3(9, 4, BB), 128>>>();      // all 216 rows
    softmax_kernel<<<BB * 216, 128>>>(216);
    gemm_big<1><<<dim3(6, 4, BB), 128>>>();      // T = P @ X
    vout_head<<<BB * HH, 256>>>(wqkv);
    gemm_flat<1><<<dim3(12, 5), 256>>>(wproj, BB * 18, 1.f, bproj, out);
}

// round 16
// speedup vs baseline: 2.6802x; 1.3142x over previous
#include <cuda_runtime.h>
#include <math.h>

#define BB 16
#define NN 1026
#define NGT 1024
#define CC 768
#define HH 12
#define XST 1040   // xln rows per batch (padded; pad rows stay zero)
#define LP 1040    // padded logit row length
// row-in-batch layout for qw/L/T:  m = r*12 + h   (r-major)

// ---- scratch (device globals; zero-init; NEVER passed as kernel args from host) ----
__device__ __align__(128) float g_xln[BB * XST * CC];
__device__ __align__(128) float g_x18[BB * 18 * CC];
__device__ __align__(128) float g_q18[BB * 18 * CC];
__device__ __align__(128) float g_qw[BB * 216 * CC];
__device__ __align__(128) float g_L[BB * 216 * LP];
__device__ __align__(128) float g_T[BB * 216 * CC];
__device__ __align__(128) float g_att[BB * 18 * CC];
__device__ __align__(128) float g_base[BB * 18 * CC];
__device__ __align__(128) int   g_idx[BB * 16];

// ---------------- kernel 1: layernorm over all 16416 tokens ----------------
__global__ void ln_kernel(const float* __restrict__ gen, const float* __restrict__ cls,
                          const float* __restrict__ box, const float* __restrict__ gamma,
                          const float* __restrict__ beta) {
    int tkn = blockIdx.x;
    int b = tkn / NN, n = tkn % NN;
    const float* src;
    if (n == 0)      src = cls + (size_t)b * CC;
    else if (n == 1) src = box + (size_t)b * CC;
    else             src = gen + ((size_t)b * NGT + (n - 2)) * CC;

    int t = threadIdx.x;
    float v[3];
    float s = 0.f, ss = 0.f;
#pragma unroll
    for (int i = 0; i < 3; i++) {
        v[i] = src[t + i * 256];
        s += v[i];
        ss += v[i] * v[i];
    }
    __shared__ float rs[8], rss[8], stat[2];
    for (int o = 16; o > 0; o >>= 1) {
        s  += __shfl_xor_sync(0xffffffffu, s, o);
        ss += __shfl_xor_sync(0xffffffffu, ss, o);
    }
    if ((t & 31) == 0) { rs[t >> 5] = s; rss[t >> 5] = ss; }
    __syncthreads();
    if (t == 0) {
        float S = 0.f, SS = 0.f;
        for (int i = 0; i < 8; i++) { S += rs[i]; SS += rss[i]; }
        float m = S / (float)CC;
        float var = SS / (float)CC - m * m;
        stat[0] = m;
        stat[1] = rsqrtf(var + 1e-5f);
    }
    __syncthreads();
    float m = stat[0], inv = stat[1];
    float* dst = g_xln + ((size_t)b * XST + n) * CC;
#pragma unroll
    for (int i = 0; i < 3; i++) {
        int c = t + i * 256;
        float y = (v[i] - m) * inv * gamma[c] + beta[c];
        dst[c] = y;
        if (n < 2) g_x18[((size_t)(b * 18 + n)) * CC + c] = y;
    }
}

// ---------------- softmax over NN keys of g_L rows (in place, pad-zeroed) -------------
// blockIdx.x = b*S + m ; L row = b*216 + m ; r = m/12 (r-major layout)
__global__ void softmax_kernel(int S) {
    int b = blockIdx.x / S, m = blockIdx.x % S;
    int r = m / 12;
    int t = threadIdx.x;
    float* L = g_L + (size_t)(b * 216 + m) * LP;
    float v[9];
    float mx = -1e30f;
#pragma unroll
    for (int i = 0; i < 9; i++) {
        int j = t + (i << 7);
        if (j < NN) {
            float x = L[j];
            if (r == 0 && j == 1) x = 0.f;
            if (r == 1 && j == 0) x = 0.f;
            v[i] = x;
            mx = fmaxf(mx, x);
        } else v[i] = -1e30f;
    }
    __shared__ float sm_[4], ss_[4];
    int w = t >> 5, lane = t & 31;
    for (int o = 16; o > 0; o >>= 1) mx = fmaxf(mx, __shfl_xor_sync(0xffffffffu, mx, o));
    if (lane == 0) sm_[w] = mx;
    __syncthreads();
    mx = fmaxf(fmaxf(sm_[0], sm_[1]), fmaxf(sm_[2], sm_[3]));
    float s = 0.f;
#pragma unroll
    for (int i = 0; i < 9; i++) {
        int j = t + (i << 7);
        if (j < NN) { v[i] = expf(v[i] - mx); s += v[i]; }
    }
    for (int o = 16; o > 0; o >>= 1) s += __shfl_xor_sync(0xffffffffu, s, o);
    if (lane == 0) ss_[w] = s;
    __syncthreads();
    float inv = 1.f / (ss_[0] + ss_[1] + ss_[2] + ss_[3]);
#pragma unroll
    for (int i = 0; i < 9; i++) {
        int j = t + (i << 7);
        if (j < NN) L[j] = v[i] * inv;
    }
    if (t < LP - NN) L[NN + t] = 0.f;
}

// ---------------- routing: bitonic sort + serial slot fill (proven) ----------
__global__ void route_kernel(const float* __restrict__ gen, const float* __restrict__ cls,
                             const float* __restrict__ box) {
    int b = blockIdx.x;
    int t = threadIdx.x;  // 1024 threads
    __shared__ unsigned long long key[NGT];
    __shared__ unsigned char sbox[NGT];
    __shared__ int sidx[16];

    float c = 0.f, bx = 0.f;
#pragma unroll
    for (int h = 0; h < HH; h++) {
        c  += g_L[((size_t)(b * 216 + h)) * LP + 2 + t];
        bx += g_L[((size_t)(b * 216 + 12 + h)) * LP + 2 + t];
    }
    float sum = c + bx;                    // positive -> float bits order == value order
    sbox[t] = (bx > c) ? 1 : 0;
    key[t] = ((unsigned long long)__float_as_uint(sum) << 32) |
             (unsigned long long)(0xFFFFFFFFu - (unsigned)t);   // stable ties
    __syncthreads();

    for (int k = 2; k <= NGT; k <<= 1)
        for (int j = k >> 1; j > 0; j >>= 1) {
            int ixj = t ^ j;
            if (ixj > t) {
                unsigned long long a = key[t], d2 = key[ixj];
                bool desc = ((t & k) == 0);
                if (desc ? (a < d2) : (a > d2)) { key[t] = d2; key[ixj] = a; }
            }
            __syncthreads();
        }

    if (t == 0) {
        int bj[16], cj[16];
        for (int i = 0; i < 16; i++) { bj[i] = -1; cj[i] = -1; }
        int br = 0, cr = 0;
        for (int p = 0; p < NGT; p++) {
            int orig = (int)(0xFFFFFFFFu - (unsigned)key[p]);
            if (sbox[orig]) { if (br < 16) bj[br] = p; br++; }
            else            { if (cr < 16) cj[15 - cr] = p; cr++; }
        }
        for (int s = 0; s < 16; s++) {
            int win = bj[s] > cj[s] ? bj[s] : cj[s];
            int id = 0;
            if (win >= 0) id = (int)(0xFFFFFFFFu - (unsigned)key[win]);
            sidx[s] = id;
            g_idx[b * 16 + s] = id;
        }
    }
    __syncthreads();

    for (int i = t; i < 18 * CC; i += 1024) {     // residual base (original tokens)
        int k = i / CC, cc2 = i % CC;
        float v;
        if (k == 0)      v = cls[(size_t)b * CC + cc2];
        else if (k == 1) v = box[(size_t)b * CC + cc2];
        else             v = gen[((size_t)b * NGT + sidx[k - 2]) * CC + cc2];
        g_base[((size_t)(b * 18 + k)) * CC + cc2] = v;
    }
    for (int i = t; i < 16 * CC; i += 1024) {     // x18 rows 2..17 (layernormed)
        int s = i / CC, cc2 = i % CC;
        g_x18[((size_t)(b * 18 + 2 + s)) * CC + cc2] =
            g_xln[((size_t)b * XST + 2 + sidx[s]) * CC + cc2];
    }
}

// ---------------- small GEMM (64x64 tile): C = scale * A @ W^T (N=K=768) --------------
template <int EPI>
__global__ void gemm_flat(const float* __restrict__ Bm, int M, float scale,
                          const float* __restrict__ bias, float* __restrict__ outp) {
    __shared__ float As[16][64];
    __shared__ float Bs[16][64];
    int t = threadIdx.x;
    int mb = blockIdx.y * 64, nb = blockIdx.x * 64;
    int lr = t >> 2, lc = (t & 3) << 2;
    int tx = t & 15, ty = t >> 4;
    float acc[4][4];
#pragma unroll
    for (int i = 0; i < 4; i++)
#pragma unroll
        for (int j = 0; j < 4; j++) acc[i][j] = 0.f;

    const float* A = EPI ? g_att : g_x18;          // device-side binding
    const float* Ap = A + (size_t)(mb + lr) * CC + lc;
    const float* Bp = Bm + (size_t)(nb + lr) * CC + lc;
    bool avalid = (mb + lr) < M;

    for (int kk = 0; kk < CC; kk += 16) {
        float4 av = avalid ? *(const float4*)(Ap + kk) : make_float4(0.f, 0.f, 0.f, 0.f);
        float4 bv = *(const float4*)(Bp + kk);
        As[lc + 0][lr] = av.x; As[lc + 1][lr] = av.y; As[lc + 2][lr] = av.z; As[lc + 3][lr] = av.w;
        Bs[lc + 0][lr] = bv.x; Bs[lc + 1][lr] = bv.y; Bs[lc + 2][lr] = bv.z; Bs[lc + 3][lr] = bv.w;
        __syncthreads();
#pragma unroll
        for (int k = 0; k < 16; k++) {
            float4 a = *(const float4*)&As[k][ty << 2];
            float4 bq = *(const float4*)&Bs[k][tx << 2];
            float aa[4] = {a.x, a.y, a.z, a.w};
            float bb[4] = {bq.x, bq.y, bq.z, bq.w};
#pragma unroll
            for (int i = 0; i < 4; i++)
#pragma unroll
                for (int j = 0; j < 4; j++) acc[i][j] += aa[i] * bb[j];
        }
        __syncthreads();
    }

#pragma unroll
    for (int i = 0; i < 4; i++) {
        int row = mb + (ty << 2) + i;
        if (row < M) {
            if (EPI == 0) {
                float* cp = g_q18 + (size_t)row * CC + nb + (tx << 2);
#pragma unroll
                for (int j = 0; j < 4; j++) cp[j] = acc[i][j] * scale;
            } else {
                int b = row / 18, k = row % 18;
                size_t off;
                if (k == 0)      off = (size_t)(b * 9) * CC;
                else if (k == 1) off = (size_t)(144 + b * 9) * CC;
                else if (k < 10) off = (size_t)(b * 9 + (k - 1)) * CC;
                else             off = (size_t)(144 + b * 9 + (k - 9)) * CC;
#pragma unroll
                for (int j = 0; j < 4; j++) {
                    int n = nb + (tx << 2) + j;
                    outp[off + n] = acc[i][j] + bias[n] + g_base[(size_t)row * CC + n];
                }
            }
        }
    }
}

// ---------------- per-head: qw = q18_h (18x64) @ Wk_h (64x768), r-major store ----------
__global__ void qw_head(const float* __restrict__ wqkv) {
    __shared__ float Ast[64][19];
    __shared__ float Wt[64][64];
    int t = threadIdx.x;
    int z = blockIdx.y;
    int b = z / HH, h = z % HH;
    int nb = blockIdx.x * 64;
    for (int i = t; i < 18 * 64; i += 256) {
        int r = i >> 6, d = i & 63;
        Ast[d][r] = g_q18[((size_t)(b * 18 + r)) * CC + h * 64 + d];
    }
    {
        int d = t >> 2, c0 = (t & 3) << 4;
        const float* wp = wqkv + ((size_t)(CC + h * 64 + d)) * CC + nb + c0;
        *(float4*)&Wt[d][c0]      = *(const float4*)wp;
        *(float4*)&Wt[d][c0 + 4]  = *(const float4*)(wp + 4);
        *(float4*)&Wt[d][c0 + 8]  = *(const float4*)(wp + 8);
        *(float4*)&Wt[d][c0 + 12] = *(const float4*)(wp + 12);
    }
    __syncthreads();
    int tx = t & 63, ty = t >> 6;
    float acc[5] = {0.f, 0.f, 0.f, 0.f, 0.f};
    for (int d = 0; d < 64; d++) {
        float w = Wt[d][tx];
#pragma unroll
        for (int i = 0; i < 5; i++) {
            int r = ty + (i << 2);
            if (r < 18) acc[i] += Ast[d][r] * w;
        }
    }
#pragma unroll
    for (int i = 0; i < 5; i++) {
        int r = ty + (i << 2);
        if (r < 18) g_qw[((size_t)(b * 216 + r * HH + h)) * CC + nb + tx] = acc[i];  // r-major
    }
}

// ---------------- per-head: out = T_h (18x768) @ Wv_h^T (768x64), r-major read --------
__global__ void vout_head(const float* __restrict__ wqkv) {
    __shared__ float Tt[18][64];
    __shared__ float Wt[64][65];   // 65-pad; scalar stores only (stride not 16B-aligned)
    int t = threadIdx.x;
    int z = blockIdx.x;
    int b = z / HH, h = z % HH;
    int tx = t & 63, ty = t >> 6;
    float acc[5] = {0.f, 0.f, 0.f, 0.f, 0.f};
    for (int cp = 0; cp < CC; cp += 64) {
        __syncthreads();
        for (int i = t; i < 18 * 64; i += 256) {
            int r = i >> 6, cc = i & 63;
            Tt[r][cc] = g_T[((size_t)(b * 216 + r * HH + h)) * CC + cp + cc];  // r-major
        }
        {
            int n = t >> 2, c0 = (t & 3) << 4;
            const float* wp = wqkv + ((size_t)(2 * CC + h * 64 + n)) * CC + cp + c0;
            float4 w0 = *(const float4*)wp;
            float4 w1 = *(const float4*)(wp + 4);
            float4 w2 = *(const float4*)(wp + 8);
            float4 w3 = *(const float4*)(wp + 12);
            Wt[n][c0 + 0]  = w0.x; Wt[n][c0 + 1]  = w0.y; Wt[n][c0 + 2]  = w0.z; Wt[n][c0 + 3]  = w0.w;
            Wt[n][c0 + 4]  = w1.x; Wt[n][c0 + 5]  = w1.y; Wt[n][c0 + 6]  = w1.z; Wt[n][c0 + 7]  = w1.w;
            Wt[n][c0 + 8]  = w2.x; Wt[n][c0 + 9]  = w2.y; Wt[n][c0 + 10] = w2.z; Wt[n][c0 + 11] = w2.w;
            Wt[n][c0 + 12] = w3.x; Wt[n][c0 + 13] = w3.y; Wt[n][c0 + 14] = w3.z; Wt[n][c0 + 15] = w3.w;
        }
        __syncthreads();
        for (int cc = 0; cc < 64; cc++) {
            float w = Wt[tx][cc];
#pragma unroll
            for (int i = 0; i < 5; i++) {
                int r = ty + (i << 2);
                if (r < 18) acc[i] += Tt[r][cc] * w;
            }
        }
    }
#pragma unroll
    for (int i = 0; i < 5; i++) {
        int r = ty + (i << 2);
        if (r < 18) g_att[((size_t)(b * 18 + r)) * CC + h * 64 + tx] = acc[i];
    }
}

// ---------------- big batched GEMM fp32 (pass 1 only; routing-critical) ----------
// MODE 0: L = qw @ Xln^T   (TB=1, N=LP guarded)
template <int MODE>
__global__ void gemm_big() {
    constexpr int M   = 216;
    constexpr int N   = LP;
    constexpr int K   = CC;
    constexpr int lda = CC;
    constexpr int ldb = CC;
    constexpr int ldc = LP;

    __shared__ float As[16][68];
    __shared__ float Bs[16][132];
    int t = threadIdx.x;
    int z = blockIdx.z;
    const float* A  = g_qw + (size_t)z * 216 * lda;
    const float* Bm = g_xln + (size_t)z * XST * CC;
    float*       C  = g_L + (size_t)z * 216 * ldc;
    int mb = blockIdx.y * 64, nb = blockIdx.x * 128;

    int ar = t >> 1, ak = (t & 1) << 3;
    bool aval = (mb + ar) < M;
    const float* Ap = A + (size_t)(mb + ar) * lda + ak;

    bool bval = (nb + t) < N;
    const float* Bp = Bm + (size_t)(nb + t) * ldb;

    float4 z4 = make_float4(0.f, 0.f, 0.f, 0.f);
    float4 a0, a1, b0, b1, b2, b3;
    a0 = aval ? *(const float4*)(Ap)     : z4;
    a1 = aval ? *(const float4*)(Ap + 4) : z4;
    b0 = bval ? *(const float4*)(Bp)      : z4;
    b1 = bval ? *(const float4*)(Bp + 4)  : z4;
    b2 = bval ? *(const float4*)(Bp + 8)  : z4;
    b3 = bval ? *(const float4*)(Bp + 12) : z4;

    int tx = t & 15, ty = t >> 4;
    int m0 = ty << 3, n0 = tx << 3;
    float acc[8][8];
#pragma unroll
    for (int i = 0; i < 8; i++)
#pragma unroll
        for (int j = 0; j < 8; j++) acc[i][j] = 0.f;

    for (int kk = 0; kk < K; kk += 16) {
        As[ak + 0][ar] = a0.x; As[ak + 1][ar] = a0.y; As[ak + 2][ar] = a0.z; As[ak + 3][ar] = a0.w;
        As[ak + 4][ar] = a1.x; As[ak + 5][ar] = a1.y; As[ak + 6][ar] = a1.z; As[ak + 7][ar] = a1.w;
        Bs[0][t] = b0.x;  Bs[1][t] = b0.y;  Bs[2][t] = b0.z;  Bs[3][t] = b0.w;
        Bs[4][t] = b1.x;  Bs[5][t] = b1.y;  Bs[6][t] = b1.z;  Bs[7][t] = b1.w;
        Bs[8][t] = b2.x;  Bs[9][t] = b2.y;  Bs[10][t] = b2.z; Bs[11][t] = b2.w;
        Bs[12][t] = b3.x; Bs[13][t] = b3.y; Bs[14][t] = b3.z; Bs[15][t] = b3.w;
        __syncthreads();
        int kn = kk + 16;
        if (kn < K) {
            a0 = aval ? *(const float4*)(Ap + kn)     : z4;
            a1 = aval ? *(const float4*)(Ap + kn + 4) : z4;
            b0 = bval ? *(const float4*)(Bp + kn)      : z4;
            b1 = bval ? *(const float4*)(Bp + kn + 4)  : z4;
            b2 = bval ? *(const float4*)(Bp + kn + 8)  : z4;
            b3 = bval ? *(const float4*)(Bp + kn + 12) : z4;
        }
#pragma unroll
        for (int k = 0; k < 16; k++) {
            float am[8], bn_[8];
            *(float4*)&am[0]  = *(const float4*)&As[k][m0];
            *(float4*)&am[4]  = *(const float4*)&As[k][m0 + 4];
            *(float4*)&bn_[0] = *(const float4*)&Bs[k][n0];
            *(float4*)&bn_[4] = *(const float4*)&Bs[k][n0 + 4];
#pragma unroll
            for (int i = 0; i < 8; i++)
#pragma unroll
                for (int j = 0; j < 8; j++) acc[i][j] += am[i] * bn_[j];
        }
        __syncthreads();
    }

#pragma unroll
    for (int i = 0; i < 8; i++) {
        int row = mb + m0 + i;
        if (row < M) {
            float* cp = C + (size_t)row * ldc + nb + n0;
#pragma unroll
            for (int j = 0; j < 8; j++)
                if (nb + n0 + j < N) cp[j] = acc[i][j];
        }
    }
}

// ---------------- tf32 tensor-core GEMM (pass 2): 64x128 tile, 4 warps ----------------
// MODE 0: L = qw @ Xln^T  (B source [n][k]; N=LP guarded)
// MODE 1: T = P(L) @ Xln  (B source [k][n]; N=CC exact)
__device__ __forceinline__ unsigned f2tf(float x) {
    unsigned r;
    asm("cvt.rna.tf32.f32 %0, %1;" : "=r"(r) : "f"(x));
    return r;
}

template <int MODE>
__global__ void gemm_mma() {
    constexpr int M   = 216;
    constexpr int N   = (MODE == 0) ? LP : CC;
    constexpr int K   = (MODE == 0) ? CC : LP;
    constexpr int lda = (MODE == 0) ? CC : LP;
    constexpr int ldb = CC;
    constexpr int ldc = (MODE == 0) ? LP : CC;

    __shared__ float As[16][72];    // [k][m], tf32 bits
    __shared__ float Bs[16][136];   // [k][n], tf32 bits
    int t = threadIdx.x;
    int z = blockIdx.z;
    const float* A  = ((MODE == 0) ? g_qw : g_L) + (size_t)z * 216 * lda;
    const float* Bm = g_xln + (size_t)z * XST * CC;
    float*       C  = ((MODE == 0) ? g_L : g_T) + (size_t)z * 216 * ldc;
    int mb = blockIdx.y * 64, nb = blockIdx.x * 128;

    // A loader: row ar (0..63), k-offset ak (0 or 8)
    int ar = t >> 1, ak = (t & 1) << 3;
    bool aval = (mb + ar) < M;
    const float* Ap = A + (size_t)(mb + ar) * lda + ak;

    // B loader
    const float* Bp;
    bool bval = true;
    int bk = 0, bn = 0;
    if (MODE == 0) {
        bval = (nb + t) < N;
        Bp = Bm + (size_t)(nb + t) * ldb;
    } else {
        bk = t >> 3; bn = (t & 7) << 4;
        Bp = Bm + (size_t)bk * ldb + nb + bn;
    }

    float4 z4 = make_float4(0.f, 0.f, 0.f, 0.f);
    float4 a0, a1, b0, b1, b2, b3;
    a0 = aval ? *(const float4*)(Ap)     : z4;
    a1 = aval ? *(const float4*)(Ap + 4) : z4;
    if (MODE == 0) {
        b0 = bval ? *(const float4*)(Bp)      : z4;
        b1 = bval ? *(const float4*)(Bp + 4)  : z4;
        b2 = bval ? *(const float4*)(Bp + 8)  : z4;
        b3 = bval ? *(const float4*)(Bp + 12) : z4;
    } else {
        b0 = *(const float4*)(Bp);
        b1 = *(const float4*)(Bp + 4);
        b2 = *(const float4*)(Bp + 8);
        b3 = *(const float4*)(Bp + 12);
    }

    int lane = t & 31, w = t >> 5;
    int gid = lane >> 2, tig = lane & 3;
    float c[4][4][4];
#pragma unroll
    for (int mt = 0; mt < 4; mt++)
#pragma unroll
        for (int nt = 0; nt < 4; nt++)
#pragma unroll
            for (int i = 0; i < 4; i++) c[mt][nt][i] = 0.f;

    for (int kk = 0; kk < K; kk += 16) {
        // stage tiles (convert to tf32 bits once)
        As[ak + 0][ar] = __uint_as_float(f2tf(a0.x));
        As[ak + 1][ar] = __uint_as_float(f2tf(a0.y));
        As[ak + 2][ar] = __uint_as_float(f2tf(a0.z));
        As[ak + 3][ar] = __uint_as_float(f2tf(a0.w));
        As[ak + 4][ar] = __uint_as_float(f2tf(a1.x));
        As[ak + 5][ar] = __uint_as_float(f2tf(a1.y));
        As[ak + 6][ar] = __uint_as_float(f2tf(a1.z));
        As[ak + 7][ar] = __uint_as_float(f2tf(a1.w));
        if (MODE == 0) {
            Bs[0][t]  = __uint_as_float(f2tf(b0.x)); Bs[1][t]  = __uint_as_float(f2tf(b0.y));
            Bs[2][t]  = __uint_as_float(f2tf(b0.z)); Bs[3][t]  = __uint_as_float(f2tf(b0.w));
            Bs[4][t]  = __uint_as_float(f2tf(b1.x)); Bs[5][t]  = __uint_as_float(f2tf(b1.y));
            Bs[6][t]  = __uint_as_float(f2tf(b1.z)); Bs[7][t]  = __uint_as_float(f2tf(b1.w));
            Bs[8][t]  = __uint_as_float(f2tf(b2.x)); Bs[9][t]  = __uint_as_float(f2tf(b2.y));
            Bs[10][t] = __uint_as_float(f2tf(b2.z)); Bs[11][t] = __uint_as_float(f2tf(b2.w));
            Bs[12][t] = __uint_as_float(f2tf(b3.x)); Bs[13][t] = __uint_as_float(f2tf(b3.y));
            Bs[14][t] = __uint_as_float(f2tf(b3.z)); Bs[15][t] = __uint_as_float(f2tf(b3.w));
        } else {
            float4 c0v = make_float4(__uint_as_float(f2tf(b0.x)), __uint_as_float(f2tf(b0.y)),
                                     __uint_as_float(f2tf(b0.z)), __uint_as_float(f2tf(b0.w)));
            float4 c1v = make_float4(__uint_as_float(f2tf(b1.x)), __uint_as_float(f2tf(b1.y)),
                                     __uint_as_float(f2tf(b1.z)), __uint_as_float(f2tf(b1.w)));
            float4 c2v = make_float4(__uint_as_float(f2tf(b2.x)), __uint_as_float(f2tf(b2.y)),
                                     __uint_as_float(f2tf(b2.z)), __uint_as_float(f2tf(b2.w)));
            float4 c3v = make_float4(__uint_as_float(f2tf(b3.x)), __uint_as_float(f2tf(b3.y)),
                                     __uint_as_float(f2tf(b3.z)), __uint_as_float(f2tf(b3.w)));
            *(float4*)&Bs[bk][bn]      = c0v;
            *(float4*)&Bs[bk][bn + 4]  = c1v;
            *(float4*)&Bs[bk][bn + 8]  = c2v;
            *(float4*)&Bs[bk][bn + 12] = c3v;
        }
        __syncthreads();

        int kn = kk + 16;
        if (kn < K) {  // prefetch next tile
            a0 = aval ? *(const float4*)(Ap + kn)     : z4;
            a1 = aval ? *(const float4*)(Ap + kn + 4) : z4;
            if (MODE == 0) {
                b0 = bval ? *(const float4*)(Bp + kn)      : z4;
                b1 = bval ? *(const float4*)(Bp + kn + 4)  : z4;
                b2 = bval ? *(const float4*)(Bp + kn + 8)  : z4;
                b3 = bval ? *(const float4*)(Bp + kn + 12) : z4;
            } else {
                const float* bq = Bp + (size_t)kn * ldb;
                b0 = *(const float4*)(bq);
                b1 = *(const float4*)(bq + 4);
                b2 = *(const float4*)(bq + 8);
                b3 = *(const float4*)(bq + 12);
            }
        }

#pragma unroll
        for (int ks = 0; ks < 2; ks++) {
            int k0 = ks << 3;
            unsigned bf[4][2];
#pragma unroll
            for (int nt = 0; nt < 4; nt++) {
                int ncol = (w << 5) + (nt << 3) + gid;
                bf[nt][0] = __float_as_uint(Bs[k0 + tig][ncol]);
                bf[nt][1] = __float_as_uint(Bs[k0 + tig + 4][ncol]);
            }
#pragma unroll
            for (int mt = 0; mt < 4; mt++) {
                int mr = (mt << 4) + gid;
                unsigned af0 = __float_as_uint(As[k0 + tig][mr]);
                unsigned af1 = __float_as_uint(As[k0 + tig][mr + 8]);
                unsigned af2 = __float_as_uint(As[k0 + tig + 4][mr]);
                unsigned af3 = __float_as_uint(As[k0 + tig + 4][mr + 8]);
#pragma unroll
                for (int nt = 0; nt < 4; nt++) {
                    asm volatile(
                        "mma.sync.aligned.m16n8k8.row.col.f32.tf32.tf32.f32 "
                        "{%0,%1,%2,%3}, {%4,%5,%6,%7}, {%8,%9}, {%0,%1,%2,%3};"
                        : "+f"(c[mt][nt][0]), "+f"(c[mt][nt][1]),
                          "+f"(c[mt][nt][2]), "+f"(c[mt][nt][3])
                        : "r"(af0), "r"(af1), "r"(af2), "r"(af3),
                          "r"(bf[nt][0]), "r"(bf[nt][1]));
                }
            }
        }
        __syncthreads();
    }

    // epilogue: c0,c1 at (row, col..col+1); c2,c3 at (row+8, ...)
#pragma unroll
    for (int mt = 0; mt < 4; mt++) {
        int row0 = mb + (mt << 4) + gid;
#pragma unroll
        for (int nt = 0; nt < 4; nt++) {
            int col = nb + (w << 5) + (nt << 3) + (tig << 1);
            bool cok = (MODE == 1) || (col < N);   // col even, N even -> col+1 ok too
#pragma unroll
            for (int half = 0; half < 2; half++) {
                int row = row0 + (half << 3);
                if (row < M && cok) {
                    float* cp = C + (size_t)row * ldc + col;
                    cp[0] = c[mt][nt][(half << 1) + 0];
                    cp[1] = c[mt][nt][(half << 1) + 1];
                }
            }
        }
    }
}

// ---------------- launch ----------------
extern "C" void kernel_launch(void* const* d_in, const int* in_sizes, int n_in,
                              void* d_out, int out_size) {
    const float* gen   = (const float*)d_in[0];
    const float* cls   = (const float*)d_in[1];
    const float* box   = (const float*)d_in[2];
    const float* wqkv  = (const float*)d_in[3];
    const float* wproj = (const float*)d_in[4];
    const float* bproj = (const float*)d_in[5];
    const float* gamma = (const float*)d_in[6];
    const float* beta  = (const float*)d_in[7];
    float* out = (float*)d_out;

    // 1. LayerNorm (stages x18 rows 0,1)
    ln_kernel<<<BB * NN, 256>>>(gen, cls, box, gamma, beta);

    // ---- PASS 1 (fp32 logits; routing-critical, unchanged) ----
    gemm_flat<0><<<dim3(12, 5), 256>>>(wqkv, BB * 18, 0.125f, nullptr, nullptr);
    qw_head<<<dim3(12, BB * HH), 256>>>(wqkv);
    gemm_big<0><<<dim3(9, 1, BB), 128>>>();      // m-tile 0 only (rows 0..63)
    softmax_kernel<<<BB * 24, 128>>>(24);        // rows m=0..23 (r=0,1 all heads)

    // 2. Routing + gathers
    route_kernel<<<BB, 1024>>>(gen, cls, box);

    // ---- PASS 2 (tf32 tensor cores for the two big GEMMs) ----
    gemm_flat<0><<<dim3(12, 5), 256>>>(wqkv, BB * 18, 0.125f, nullptr, nullptr);
    qw_head<<<dim3(12, BB * HH), 256>>>(wqkv);
    gemm_mma<0><<<dim3(9, 4, BB), 128>>>();      // L = qw @ X^T (tf32)
    softmax_kernel<<<BB * 216, 128>>>(216);
    gemm_mma<1><<<dim3(6, 4, BB), 128>>>();      // T = P @ X (tf32)
    vout_head<<<BB * HH, 256>>>(wqkv);
    gemm_flat<1><<<dim3(12, 5), 256>>>(wproj, BB * 18, 1.f, bproj, out);
}

// round 17
// speedup vs baseline: 2.8066x; 1.0471x over previous
#include <cuda_runtime.h>
#include <math.h>

#define BB 16
#define NN 1026
#define NGT 1024
#define CC 768
#define HH 12
#define XST 1040   // xln rows per batch (padded; pad rows stay zero)
#define LP 1040    // padded logit row length
// row-in-batch layout for qw/L/T:  m = r*12 + h   (r-major)

// ---- scratch (device globals; zero-init; NEVER passed as kernel args from host) ----
__device__ __align__(128) float g_xln[BB * XST * CC];
__device__ __align__(128) float g_x18[BB * 18 * CC];
__device__ __align__(128) float g_q18[BB * 18 * CC];
__device__ __align__(128) float g_qw[BB * 216 * CC];
__device__ __align__(128) float g_L[BB * 216 * LP];
__device__ __align__(128) float g_T[BB * 216 * CC];
__device__ __align__(128) float g_att[BB * 18 * CC];
__device__ __align__(128) float g_base[BB * 18 * CC];
__device__ __align__(128) int   g_idx[BB * 16];

// ---------------- kernel 1: layernorm over all 16416 tokens ----------------
__global__ void ln_kernel(const float* __restrict__ gen, const float* __restrict__ cls,
                          const float* __restrict__ box, const float* __restrict__ gamma,
                          const float* __restrict__ beta) {
    int tkn = blockIdx.x;
    int b = tkn / NN, n = tkn % NN;
    const float* src;
    if (n == 0)      src = cls + (size_t)b * CC;
    else if (n == 1) src = box + (size_t)b * CC;
    else             src = gen + ((size_t)b * NGT + (n - 2)) * CC;

    int t = threadIdx.x;
    float v[3];
    float s = 0.f, ss = 0.f;
#pragma unroll
    for (int i = 0; i < 3; i++) {
        v[i] = src[t + i * 256];
        s += v[i];
        ss += v[i] * v[i];
    }
    __shared__ float rs[8], rss[8], stat[2];
    for (int o = 16; o > 0; o >>= 1) {
        s  += __shfl_xor_sync(0xffffffffu, s, o);
        ss += __shfl_xor_sync(0xffffffffu, ss, o);
    }
    if ((t & 31) == 0) { rs[t >> 5] = s; rss[t >> 5] = ss; }
    __syncthreads();
    if (t == 0) {
        float S = 0.f, SS = 0.f;
        for (int i = 0; i < 8; i++) { S += rs[i]; SS += rss[i]; }
        float m = S / (float)CC;
        float var = SS / (float)CC - m * m;
        stat[0] = m;
        stat[1] = rsqrtf(var + 1e-5f);
    }
    __syncthreads();
    float m = stat[0], inv = stat[1];
    float* dst = g_xln + ((size_t)b * XST + n) * CC;
#pragma unroll
    for (int i = 0; i < 3; i++) {
        int c = t + i * 256;
        float y = (v[i] - m) * inv * gamma[c] + beta[c];
        dst[c] = y;
        if (n < 2) g_x18[((size_t)(b * 18 + n)) * CC + c] = y;
    }
}

// ---------------- softmax over NN keys of g_L rows (in place, pad-zeroed) -------------
// blockIdx.x = b*S + mi ; L row = b*216 + off + mi ; r = m/12 (r-major layout)
__global__ void softmax_kernel(int S, int off) {
    int b = blockIdx.x / S, m = off + blockIdx.x % S;
    int r = m / 12;
    int t = threadIdx.x;
    float* L = g_L + (size_t)(b * 216 + m) * LP;
    float v[9];
    float mx = -1e30f;
#pragma unroll
    for (int i = 0; i < 9; i++) {
        int j = t + (i << 7);
        if (j < NN) {
            float x = L[j];
            if (r == 0 && j == 1) x = 0.f;
            if (r == 1 && j == 0) x = 0.f;
            v[i] = x;
            mx = fmaxf(mx, x);
        } else v[i] = -1e30f;
    }
    __shared__ float sm_[4], ss_[4];
    int w = t >> 5, lane = t & 31;
    for (int o = 16; o > 0; o >>= 1) mx = fmaxf(mx, __shfl_xor_sync(0xffffffffu, mx, o));
    if (lane == 0) sm_[w] = mx;
    __syncthreads();
    mx = fmaxf(fmaxf(sm_[0], sm_[1]), fmaxf(sm_[2], sm_[3]));
    float s = 0.f;
#pragma unroll
    for (int i = 0; i < 9; i++) {
        int j = t + (i << 7);
        if (j < NN) { v[i] = expf(v[i] - mx); s += v[i]; }
    }
    for (int o = 16; o > 0; o >>= 1) s += __shfl_xor_sync(0xffffffffu, s, o);
    if (lane == 0) ss_[w] = s;
    __syncthreads();
    float inv = 1.f / (ss_[0] + ss_[1] + ss_[2] + ss_[3]);
#pragma unroll
    for (int i = 0; i < 9; i++) {
        int j = t + (i << 7);
        if (j < NN) L[j] = v[i] * inv;
    }
    if (t < LP - NN) L[NN + t] = 0.f;
}

// ---------------- routing: rank-count (equivalent to sort + serial slot fill) --------
// For each token: rank = #keys greater (= its descending-sort position), crank = rank
// within its category. Box cand with crank s fills slot s; cls cand with crank cr
// fills slot 15-cr; winner = larger sort position (later overwrite in the serial loop).
__global__ void route_kernel(const float* __restrict__ gen, const float* __restrict__ cls,
                             const float* __restrict__ box) {
    int b = blockIdx.x;
    int t = threadIdx.x;  // 1024 threads
    __shared__ unsigned long long skey[NGT];
    __shared__ unsigned char sflag[NGT];
    __shared__ int bR[16], bT[16], cR[16], cT[16], sidx[16];

    float c = 0.f, bx = 0.f;
#pragma unroll
    for (int h = 0; h < HH; h++) {
        c  += g_L[((size_t)(b * 216 + h)) * LP + 2 + t];
        bx += g_L[((size_t)(b * 216 + 12 + h)) * LP + 2 + t];
    }
    unsigned char f = (bx > c) ? 1 : 0;
    // positive sums: float-bit order == value order; tiebreak = lower index first
    unsigned long long myk = ((unsigned long long)__float_as_uint(c + bx) << 32) |
                             (unsigned long long)(0xFFFFFFFFu - (unsigned)t);
    skey[t] = myk;
    sflag[t] = f;
    if (t < 16) { bR[t] = -1; bT[t] = 0; cR[t] = -1; cT[t] = 0; }
    __syncthreads();

    int rank = 0, crank = 0;
#pragma unroll 8
    for (int j = 0; j < NGT; j++) {
        bool gt = skey[j] > myk;
        rank += gt ? 1 : 0;
        crank += (gt && sflag[j] == f) ? 1 : 0;
    }
    if (crank < 16) {
        if (f) { bR[crank] = rank; bT[crank] = t; }
        else   { cR[15 - crank] = rank; cT[15 - crank] = t; }
    }
    __syncthreads();
    if (t < 16) {
        int id = 0;
        if (bR[t] >= 0 || cR[t] >= 0) id = (bR[t] > cR[t]) ? bT[t] : cT[t];
        sidx[t] = id;
        g_idx[b * 16 + t] = id;
    }
    __syncthreads();

    for (int i = t; i < 18 * CC; i += 1024) {     // residual base (original tokens)
        int k = i / CC, cc2 = i % CC;
        float v;
        if (k == 0)      v = cls[(size_t)b * CC + cc2];
        else if (k == 1) v = box[(size_t)b * CC + cc2];
        else             v = gen[((size_t)b * NGT + sidx[k - 2]) * CC + cc2];
        g_base[((size_t)(b * 18 + k)) * CC + cc2] = v;
    }
    for (int i = t; i < 16 * CC; i += 1024) {     // x18 rows 2..17 (layernormed)
        int s = i / CC, cc2 = i % CC;
        g_x18[((size_t)(b * 18 + 2 + s)) * CC + cc2] =
            g_xln[((size_t)b * XST + 2 + sidx[s]) * CC + cc2];
    }
}

// ---------------- small GEMM (64x64 tile): C = scale * A @ W^T (N=K=768) --------------
template <int EPI>
__global__ void gemm_flat(const float* __restrict__ Bm, int M, float scale,
                          const float* __restrict__ bias, float* __restrict__ outp) {
    __shared__ float As[16][64];
    __shared__ float Bs[16][64];
    int t = threadIdx.x;
    int mb = blockIdx.y * 64, nb = blockIdx.x * 64;
    int lr = t >> 2, lc = (t & 3) << 2;
    int tx = t & 15, ty = t >> 4;
    float acc[4][4];
#pragma unroll
    for (int i = 0; i < 4; i++)
#pragma unroll
        for (int j = 0; j < 4; j++) acc[i][j] = 0.f;

    const float* A = EPI ? g_att : g_x18;          // device-side binding
    const float* Ap = A + (size_t)(mb + lr) * CC + lc;
    const float* Bp = Bm + (size_t)(nb + lr) * CC + lc;
    bool avalid = (mb + lr) < M;

    for (int kk = 0; kk < CC; kk += 16) {
        float4 av = avalid ? *(const float4*)(Ap + kk) : make_float4(0.f, 0.f, 0.f, 0.f);
        float4 bv = *(const float4*)(Bp + kk);
        As[lc + 0][lr] = av.x; As[lc + 1][lr] = av.y; As[lc + 2][lr] = av.z; As[lc + 3][lr] = av.w;
        Bs[lc + 0][lr] = bv.x; Bs[lc + 1][lr] = bv.y; Bs[lc + 2][lr] = bv.z; Bs[lc + 3][lr] = bv.w;
        __syncthreads();
#pragma unroll
        for (int k = 0; k < 16; k++) {
            float4 a = *(const float4*)&As[k][ty << 2];
            float4 bq = *(const float4*)&Bs[k][tx << 2];
            float aa[4] = {a.x, a.y, a.z, a.w};
            float bb[4] = {bq.x, bq.y, bq.z, bq.w};
#pragma unroll
            for (int i = 0; i < 4; i++)
#pragma unroll
                for (int j = 0; j < 4; j++) acc[i][j] += aa[i] * bb[j];
        }
        __syncthreads();
    }

#pragma unroll
    for (int i = 0; i < 4; i++) {
        int row = mb + (ty << 2) + i;
        if (row < M) {
            if (EPI == 0) {
                float* cp = g_q18 + (size_t)row * CC + nb + (tx << 2);
#pragma unroll
                for (int j = 0; j < 4; j++) cp[j] = acc[i][j] * scale;
            } else {
                int b = row / 18, k = row % 18;
                size_t off;
                if (k == 0)      off = (size_t)(b * 9) * CC;
                else if (k == 1) off = (size_t)(144 + b * 9) * CC;
                else if (k < 10) off = (size_t)(b * 9 + (k - 1)) * CC;
                else             off = (size_t)(144 + b * 9 + (k - 9)) * CC;
#pragma unroll
                for (int j = 0; j < 4; j++) {
                    int n = nb + (tx << 2) + j;
                    outp[off + n] = acc[i][j] + bias[n] + g_base[(size_t)row * CC + n];
                }
            }
        }
    }
}

// ---------------- per-head: qw = q18_h (18x64) @ Wk_h (64x768), r-major store ----------
__global__ void qw_head(const float* __restrict__ wqkv) {
    __shared__ float Ast[64][19];
    __shared__ float Wt[64][64];
    int t = threadIdx.x;
    int z = blockIdx.y;
    int b = z / HH, h = z % HH;
    int nb = blockIdx.x * 64;
    for (int i = t; i < 18 * 64; i += 256) {
        int r = i >> 6, d = i & 63;
        Ast[d][r] = g_q18[((size_t)(b * 18 + r)) * CC + h * 64 + d];
    }
    {
        int d = t >> 2, c0 = (t & 3) << 4;
        const float* wp = wqkv + ((size_t)(CC + h * 64 + d)) * CC + nb + c0;
        *(float4*)&Wt[d][c0]      = *(const float4*)wp;
        *(float4*)&Wt[d][c0 + 4]  = *(const float4*)(wp + 4);
        *(float4*)&Wt[d][c0 + 8]  = *(const float4*)(wp + 8);
        *(float4*)&Wt[d][c0 + 12] = *(const float4*)(wp + 12);
    }
    __syncthreads();
    int tx = t & 63, ty = t >> 6;
    float acc[5] = {0.f, 0.f, 0.f, 0.f, 0.f};
    for (int d = 0; d < 64; d++) {
        float w = Wt[d][tx];
#pragma unroll
        for (int i = 0; i < 5; i++) {
            int r = ty + (i << 2);
            if (r < 18) acc[i] += Ast[d][r] * w;
        }
    }
#pragma unroll
    for (int i = 0; i < 5; i++) {
        int r = ty + (i << 2);
        if (r < 18) g_qw[((size_t)(b * 216 + r * HH + h)) * CC + nb + tx] = acc[i];  // r-major
    }
}

// ---------------- per-head: out = T_h (18x768) @ Wv_h^T (768x64), r-major read --------
__global__ void vout_head(const float* __restrict__ wqkv) {
    __shared__ float Tt[18][64];
    __shared__ float Wt[64][65];   // 65-pad; scalar stores only (stride not 16B-aligned)
    int t = threadIdx.x;
    int z = blockIdx.x;
    int b = z / HH, h = z % HH;
    int tx = t & 63, ty = t >> 6;
    float acc[5] = {0.f, 0.f, 0.f, 0.f, 0.f};
    for (int cp = 0; cp < CC; cp += 64) {
        __syncthreads();
        for (int i = t; i < 18 * 64; i += 256) {
            int r = i >> 6, cc = i & 63;
            Tt[r][cc] = g_T[((size_t)(b * 216 + r * HH + h)) * CC + cp + cc];  // r-major
        }
        {
            int n = t >> 2, c0 = (t & 3) << 4;
            const float* wp = wqkv + ((size_t)(2 * CC + h * 64 + n)) * CC + cp + c0;
            float4 w0 = *(const float4*)wp;
            float4 w1 = *(const float4*)(wp + 4);
            float4 w2 = *(const float4*)(wp + 8);
            float4 w3 = *(const float4*)(wp + 12);
            Wt[n][c0 + 0]  = w0.x; Wt[n][c0 + 1]  = w0.y; Wt[n][c0 + 2]  = w0.z; Wt[n][c0 + 3]  = w0.w;
            Wt[n][c0 + 4]  = w1.x; Wt[n][c0 + 5]  = w1.y; Wt[n][c0 + 6]  = w1.z; Wt[n][c0 + 7]  = w1.w;
            Wt[n][c0 + 8]  = w2.x; Wt[n][c0 + 9]  = w2.y; Wt[n][c0 + 10] = w2.z; Wt[n][c0 + 11] = w2.w;
            Wt[n][c0 + 12] = w3.x; Wt[n][c0 + 13] = w3.y; Wt[n][c0 + 14] = w3.z; Wt[n][c0 + 15] = w3.w;
        }
        __syncthreads();
        for (int cc = 0; cc < 64; cc++) {
            float w = Wt[tx][cc];
#pragma unroll
            for (int i = 0; i < 5; i++) {
                int r = ty + (i << 2);
                if (r < 18) acc[i] += Tt[r][cc] * w;
            }
        }
    }
#pragma unroll
    for (int i = 0; i < 5; i++) {
        int r = ty + (i << 2);
        if (r < 18) g_att[((size_t)(b * 18 + r)) * CC + h * 64 + tx] = acc[i];
    }
}

// ---------------- pass-1 fp32 GEMM: L rows 0..31 = qw @ Xln^T (32x128 tile) ------------
// Same k-staging order as the old 64-row kernel -> bit-identical L rows 0..23.
__global__ void gemm_p1() {
    constexpr int N = LP, K = CC;
    __shared__ float As[16][36];
    __shared__ float Bs[16][132];
    int t = threadIdx.x;
    int z = blockIdx.z;
    const float* A  = g_qw + (size_t)z * 216 * CC;
    const float* Bm = g_xln + (size_t)z * XST * CC;
    float*       C  = g_L + (size_t)z * 216 * LP;
    int nb = blockIdx.x * 128;

    int ar = t >> 2, ak = (t & 3) << 2;        // 32 rows x 4-float chunks
    const float* Ap = A + (size_t)ar * CC + ak;
    bool bval = (nb + t) < N;
    const float* Bp = Bm + (size_t)(nb + t) * CC;

    float4 z4 = make_float4(0.f, 0.f, 0.f, 0.f);
    float4 a0, b0, b1, b2, b3;
    a0 = *(const float4*)(Ap);
    b0 = bval ? *(const float4*)(Bp)      : z4;
    b1 = bval ? *(const float4*)(Bp + 4)  : z4;
    b2 = bval ? *(const float4*)(Bp + 8)  : z4;
    b3 = bval ? *(const float4*)(Bp + 12) : z4;

    int tx = t & 15, ty = t >> 4;
    int m0 = ty << 2, n0 = tx << 3;
    float acc[4][8];
#pragma unroll
    for (int i = 0; i < 4; i++)
#pragma unroll
        for (int j = 0; j < 8; j++) acc[i][j] = 0.f;

    for (int kk = 0; kk < K; kk += 16) {
        As[ak + 0][ar] = a0.x; As[ak + 1][ar] = a0.y; As[ak + 2][ar] = a0.z; As[ak + 3][ar] = a0.w;
        Bs[0][t] = b0.x;  Bs[1][t] = b0.y;  Bs[2][t] = b0.z;  Bs[3][t] = b0.w;
        Bs[4][t] = b1.x;  Bs[5][t] = b1.y;  Bs[6][t] = b1.z;  Bs[7][t] = b1.w;
        Bs[8][t] = b2.x;  Bs[9][t] = b2.y;  Bs[10][t] = b2.z; Bs[11][t] = b2.w;
        Bs[12][t] = b3.x; Bs[13][t] = b3.y; Bs[14][t] = b3.z; Bs[15][t] = b3.w;
        __syncthreads();
        int kn = kk + 16;
        if (kn < K) {
            a0 = *(const float4*)(Ap + kn);
            b0 = bval ? *(const float4*)(Bp + kn)      : z4;
            b1 = bval ? *(const float4*)(Bp + kn + 4)  : z4;
            b2 = bval ? *(const float4*)(Bp + kn + 8)  : z4;
            b3 = bval ? *(const float4*)(Bp + kn + 12) : z4;
        }
#pragma unroll
        for (int k = 0; k < 16; k++) {
            float am[4], bn_[8];
            *(float4*)&am[0]  = *(const float4*)&As[k][m0];
            *(float4*)&bn_[0] = *(const float4*)&Bs[k][n0];
            *(float4*)&bn_[4] = *(const float4*)&Bs[k][n0 + 4];
#pragma unroll
            for (int i = 0; i < 4; i++)
#pragma unroll
                for (int j = 0; j < 8; j++) acc[i][j] += am[i] * bn_[j];
        }
        __syncthreads();
    }

#pragma unroll
    for (int i = 0; i < 4; i++) {
        int row = m0 + i;                       // rows 0..31
        float* cp = C + (size_t)row * LP + nb + n0;
#pragma unroll
        for (int j = 0; j < 8; j++)
            if (nb + n0 + j < N) cp[j] = acc[i][j];
    }
}

// ---------------- tf32 tensor-core GEMM (pass 2): 64x128 tile, 4 warps ----------------
// MODE 0: L = qw @ Xln^T  (B source [n][k]; N=LP guarded), m-tiles offset by MB0
// MODE 1: T = P(L) @ Xln  (B source [k][n]; N=CC exact)
__device__ __forceinline__ unsigned f2tf(float x) {
    unsigned r;
    asm("cvt.rna.tf32.f32 %0, %1;" : "=r"(r) : "f"(x));
    return r;
}

template <int MODE, int MB0>
__global__ void gemm_mma() {
    constexpr int M   = 216;
    constexpr int N   = (MODE == 0) ? LP : CC;
    constexpr int K   = (MODE == 0) ? CC : LP;
    constexpr int lda = (MODE == 0) ? CC : LP;
    constexpr int ldb = CC;
    constexpr int ldc = (MODE == 0) ? LP : CC;

    __shared__ float As[16][72];    // [k][m], tf32 bits
    __shared__ float Bs[16][136];   // [k][n], tf32 bits
    int t = threadIdx.x;
    int z = blockIdx.z;
    const float* A  = ((MODE == 0) ? g_qw : g_L) + (size_t)z * 216 * lda;
    const float* Bm = g_xln + (size_t)z * XST * CC;
    float*       C  = ((MODE == 0) ? g_L : g_T) + (size_t)z * 216 * ldc;
    int mb = MB0 + blockIdx.y * 64, nb = blockIdx.x * 128;

    int ar = t >> 1, ak = (t & 1) << 3;
    bool aval = (mb + ar) < M;
    const float* Ap = A + (size_t)(mb + ar) * lda + ak;

    const float* Bp;
    bool bval = true;
    int bk = 0, bn = 0;
    if (MODE == 0) {
        bval = (nb + t) < N;
        Bp = Bm + (size_t)(nb + t) * ldb;
    } else {
        bk = t >> 3; bn = (t & 7) << 4;
        Bp = Bm + (size_t)bk * ldb + nb + bn;
    }

    float4 z4 = make_float4(0.f, 0.f, 0.f, 0.f);
    float4 a0, a1, b0, b1, b2, b3;
    a0 = aval ? *(const float4*)(Ap)     : z4;
    a1 = aval ? *(const float4*)(Ap + 4) : z4;
    if (MODE == 0) {
        b0 = bval ? *(const float4*)(Bp)      : z4;
        b1 = bval ? *(const float4*)(Bp + 4)  : z4;
        b2 = bval ? *(const float4*)(Bp + 8)  : z4;
        b3 = bval ? *(const float4*)(Bp + 12) : z4;
    } else {
        b0 = *(const float4*)(Bp);
        b1 = *(const float4*)(Bp + 4);
        b2 = *(const float4*)(Bp + 8);
        b3 = *(const float4*)(Bp + 12);
    }

    int lane = t & 31, w = t >> 5;
    int gid = lane >> 2, tig = lane & 3;
    float c[4][4][4];
#pragma unroll
    for (int mt = 0; mt < 4; mt++)
#pragma unroll
        for (int nt = 0; nt < 4; nt++)
#pragma unroll
            for (int i = 0; i < 4; i++) c[mt][nt][i] = 0.f;

    for (int kk = 0; kk < K; kk += 16) {
        As[ak + 0][ar] = __uint_as_float(f2tf(a0.x));
        As[ak + 1][ar] = __uint_as_float(f2tf(a0.y));
        As[ak + 2][ar] = __uint_as_float(f2tf(a0.z));
        As[ak + 3][ar] = __uint_as_float(f2tf(a0.w));
        As[ak + 4][ar] = __uint_as_float(f2tf(a1.x));
        As[ak + 5][ar] = __uint_as_float(f2tf(a1.y));
        As[ak + 6][ar] = __uint_as_float(f2tf(a1.z));
        As[ak + 7][ar] = __uint_as_float(f2tf(a1.w));
        if (MODE == 0) {
            Bs[0][t]  = __uint_as_float(f2tf(b0.x)); Bs[1][t]  = __uint_as_float(f2tf(b0.y));
            Bs[2][t]  = __uint_as_float(f2tf(b0.z)); Bs[3][t]  = __uint_as_float(f2tf(b0.w));
            Bs[4][t]  = __uint_as_float(f2tf(b1.x)); Bs[5][t]  = __uint_as_float(f2tf(b1.y));
            Bs[6][t]  = __uint_as_float(f2tf(b1.z)); Bs[7][t]  = __uint_as_float(f2tf(b1.w));
            Bs[8][t]  = __uint_as_float(f2tf(b2.x)); Bs[9][t]  = __uint_as_float(f2tf(b2.y));
            Bs[10][t] = __uint_as_float(f2tf(b2.z)); Bs[11][t] = __uint_as_float(f2tf(b2.w));
            Bs[12][t] = __uint_as_float(f2tf(b3.x)); Bs[13][t] = __uint_as_float(f2tf(b3.y));
            Bs[14][t] = __uint_as_float(f2tf(b3.z)); Bs[15][t] = __uint_as_float(f2tf(b3.w));
        } else {
            float4 c0v = make_float4(__uint_as_float(f2tf(b0.x)), __uint_as_float(f2tf(b0.y)),
                                     __uint_as_float(f2tf(b0.z)), __uint_as_float(f2tf(b0.w)));
            float4 c1v = make_float4(__uint_as_float(f2tf(b1.x)), __uint_as_float(f2tf(b1.y)),
                                     __uint_as_float(f2tf(b1.z)), __uint_as_float(f2tf(b1.w)));
            float4 c2v = make_float4(__uint_as_float(f2tf(b2.x)), __uint_as_float(f2tf(b2.y)),
                                     __uint_as_float(f2tf(b2.z)), __uint_as_float(f2tf(b2.w)));
            float4 c3v = make_float4(__uint_as_float(f2tf(b3.x)), __uint_as_float(f2tf(b3.y)),
                                     __uint_as_float(f2tf(b3.z)), __uint_as_float(f2tf(b3.w)));
            *(float4*)&Bs[bk][bn]      = c0v;
            *(float4*)&Bs[bk][bn + 4]  = c1v;
            *(float4*)&Bs[bk][bn + 8]  = c2v;
            *(float4*)&Bs[bk][bn + 12] = c3v;
        }
        __syncthreads();

        int kn = kk + 16;
        if (kn < K) {
            a0 = aval ? *(const float4*)(Ap + kn)     : z4;
            a1 = aval ? *(const float4*)(Ap + kn + 4) : z4;
            if (MODE == 0) {
                b0 = bval ? *(const float4*)(Bp + kn)      : z4;
                b1 = bval ? *(const float4*)(Bp + kn + 4)  : z4;
                b2 = bval ? *(const float4*)(Bp + kn + 8)  : z4;
                b3 = bval ? *(const float4*)(Bp + kn + 12) : z4;
            } else {
                const float* bq = Bp + (size_t)kn * ldb;
                b0 = *(const float4*)(bq);
                b1 = *(const float4*)(bq + 4);
                b2 = *(const float4*)(bq + 8);
                b3 = *(const float4*)(bq + 12);
            }
        }

#pragma unroll
        for (int ks = 0; ks < 2; ks++) {
            int k0 = ks << 3;
            unsigned bf[4][2];
#pragma unroll
            for (int nt = 0; nt < 4; nt++) {
                int ncol = (w << 5) + (nt << 3) + gid;
                bf[nt][0] = __float_as_uint(Bs[k0 + tig][ncol]);
                bf[nt][1] = __float_as_uint(Bs[k0 + tig + 4][ncol]);
            }
#pragma unroll
            for (int mt = 0; mt < 4; mt++) {
                int mr = (mt << 4) + gid;
                unsigned af0 = __float_as_uint(As[k0 + tig][mr]);
                unsigned af1 = __float_as_uint(As[k0 + tig][mr + 8]);
                unsigned af2 = __float_as_uint(As[k0 + tig + 4][mr]);
                unsigned af3 = __float_as_uint(As[k0 + tig + 4][mr + 8]);
#pragma unroll
                for (int nt = 0; nt < 4; nt++) {
                    asm volatile(
                        "mma.sync.aligned.m16n8k8.row.col.f32.tf32.tf32.f32 "
                        "{%0,%1,%2,%3}, {%4,%5,%6,%7}, {%8,%9}, {%0,%1,%2,%3};"
                        : "+f"(c[mt][nt][0]), "+f"(c[mt][nt][1]),
                          "+f"(c[mt][nt][2]), "+f"(c[mt][nt][3])
                        : "r"(af0), "r"(af1), "r"(af2), "r"(af3),
                          "r"(bf[nt][0]), "r"(bf[nt][1]));
                }
            }
        }
        __syncthreads();
    }

#pragma unroll
    for (int mt = 0; mt < 4; mt++) {
        int row0 = mb + (mt << 4) + gid;
#pragma unroll
        for (int nt = 0; nt < 4; nt++) {
            int col = nb + (w << 5) + (nt << 3) + (tig << 1);
            bool cok = (MODE == 1) || (col < N);
#pragma unroll
            for (int half = 0; half < 2; half++) {
                int row = row0 + (half << 3);
                if (row < M && cok) {
                    float* cp = C + (size_t)row * ldc + col;
                    cp[0] = c[mt][nt][(half << 1) + 0];
                    cp[1] = c[mt][nt][(half << 1) + 1];
                }
            }
        }
    }
}

// ---------------- launch ----------------
extern "C" void kernel_launch(void* const* d_in, const int* in_sizes, int n_in,
                              void* d_out, int out_size) {
    const float* gen   = (const float*)d_in[0];
    const float* cls   = (const float*)d_in[1];
    const float* box   = (const float*)d_in[2];
    const float* wqkv  = (const float*)d_in[3];
    const float* wproj = (const float*)d_in[4];
    const float* bproj = (const float*)d_in[5];
    const float* gamma = (const float*)d_in[6];
    const float* beta  = (const float*)d_in[7];
    float* out = (float*)d_out;

    // 1. LayerNorm (stages x18 rows 0,1)
    ln_kernel<<<BB * NN, 256>>>(gen, cls, box, gamma, beta);

    // ---- PASS 1 (fp32 logits rows 0..31; routing-critical) ----
    gemm_flat<0><<<dim3(12, 5), 256>>>(wqkv, BB * 18, 0.125f, nullptr, nullptr);
    qw_head<<<dim3(12, BB * HH), 256>>>(wqkv);
    gemm_p1<<<dim3(9, 1, BB), 128>>>();
    softmax_kernel<<<BB * 24, 128>>>(24, 0);     // rows m=0..23 (r=0,1 all heads)

    // 2. Routing (rank-count) + gathers
    route_kernel<<<BB, 1024>>>(gen, cls, box);

    // ---- PASS 2 (tf32 tensor cores; keeps fp32 L rows 0..23 from pass 1) ----
    gemm_flat<0><<<dim3(12, 5), 256>>>(wqkv, BB * 18, 0.125f, nullptr, nullptr);
    qw_head<<<dim3(12, BB * HH), 256>>>(wqkv);
    gemm_mma<0, 24><<<dim3(9, 3, BB), 128>>>();  // L rows 24..215 (3 x 64-row tiles)
    softmax_kernel<<<BB * 192, 128>>>(192, 24);  // rows m=24..215 (r>=2, no mask)
    gemm_mma<1, 0><<<dim3(6, 4, BB), 128>>>();   // T = P @ X (tf32)
    vout_head<<<BB * HH, 256>>>(wqkv);
    gemm_flat<1><<<dim3(12, 5), 256>>>(wproj, BB * 18, 1.f, bproj, out);
}